// round 13
// baseline (speedup 1.0000x reference)
#include <cuda_runtime.h>
#include <cuda_bf16.h>
#include <cstdint>
#include <cstddef>

// ---------------- problem constants ----------------
#define NN_NODES 10000
#define IN_C     256
#define C1       128
#define OUT_C    64
#define NE       640000
#define BKC      32             // K per mainloop chunk
#define CH1      313            // ceil(10000/32)
#define NTILES   314            // 157 m-blocks (64 rows) x 2 n-blocks (128 cols)
#define GWORK    ((long)NTILES * CH1)   // 98282 chunk-units
#define NCTAS    296            // 148 SMs x 2 CTAs/SM, one wave

// ---------------- PTX helpers ----------------
__device__ __forceinline__ uint32_t smem_u32(const void* p) {
    uint32_t a;
    asm("{ .reg .u64 t; cvta.to.shared.u64 t, %1; cvt.u32.u64 %0, t; }" : "=r"(a) : "l"(p));
    return a;
}
__device__ __forceinline__ void mma16808(float* d, const uint32_t* a, const uint32_t* b) {
    asm volatile("mma.sync.aligned.m16n8k8.row.col.f32.tf32.tf32.f32 "
                 "{%0,%1,%2,%3}, {%4,%5,%6,%7}, {%8,%9}, {%0,%1,%2,%3};"
                 : "+f"(d[0]), "+f"(d[1]), "+f"(d[2]), "+f"(d[3])
                 : "r"(a[0]), "r"(a[1]), "r"(a[2]), "r"(a[3]), "r"(b[0]), "r"(b[1]));
}
#define CVT_TF32(r, x) asm("cvt.rna.tf32.f32 %0, %1;" : "=r"(r) : "f"(x))
#define LDS32(x, a)    asm volatile("ld.shared.f32 %0, [%1];" : "=f"(x) : "r"(a))
#define CP16(dst, src) \
    asm volatile("cp.async.cg.shared.global [%0], [%1], 16;" :: "r"(dst), "l"(src))
#define CP16Z(dst, src, sz) \
    asm volatile("cp.async.cg.shared.global [%0], [%1], 16, %2;" :: "r"(dst), "l"(src), "r"(sz))
#define CP_COMMIT() asm volatile("cp.async.commit_group;")
#define CP_WAIT0()  asm volatile("cp.async.wait_group 0;")

// ---------------- scratch globals ----------------
__device__ float g_h   [NN_NODES * IN_C];   // zeroed, atomically accumulated, then final h
__device__ float g_tx1 [NN_NODES * IN_C];
__device__ float g_h2  [NN_NODES * C1];
__device__ float g_tx2 [NN_NODES * C1];
__device__ int   g_outdeg[NN_NODES];
__device__ int   g_indeg [NN_NODES];
__device__ float g_dinv  [NN_NODES];
__device__ int   g_rowstart[NN_NODES + 1];
__device__ int   g_cursor  [NN_NODES];
__device__ int   g_srcs [NE];
__device__ float g_ws   [NE];

// ---------------- preprocessing kernels ----------------
__global__ void k_zero_deg(int n) {
    int i = blockIdx.x * blockDim.x + threadIdx.x;
    if (i < n) { g_outdeg[i] = 0; g_indeg[i] = 0; }
}
__global__ void k_zeroH() {
    int i = blockIdx.x * blockDim.x + threadIdx.x;
    if (i < NN_NODES * IN_C / 4)
        reinterpret_cast<float4*>(g_h)[i] = make_float4(0.f, 0.f, 0.f, 0.f);
}
__global__ void k_count(const int* __restrict__ ei) {
    int e = blockIdx.x * blockDim.x + threadIdx.x;
    if (e < NE) {
        atomicAdd(&g_outdeg[ei[e]], 1);
        atomicAdd(&g_indeg[ei[NE + e]], 1);
    }
}
__global__ void k_dinv(int n) {
    int i = blockIdx.x * blockDim.x + threadIdx.x;
    if (i < n) {
        int d = g_outdeg[i];
        g_dinv[i] = (d > 0) ? rsqrtf((float)d) : 0.0f;
    }
}
// one-pass scan: each thread owns 10 rows
__global__ void k_scan(int n) {
    __shared__ int sh[1024];
    int t = threadIdx.x;
    const int per = 10;
    int base = t * per;
    int loc[10];
    int s = 0;
#pragma unroll
    for (int i = 0; i < per; i++) {
        int idx = base + i;
        int v = (idx < n) ? g_indeg[idx] : 0;
        loc[i] = s; s += v;
    }
    sh[t] = s;
    __syncthreads();
    for (int off = 1; off < 1024; off <<= 1) {
        int v = (t >= off) ? sh[t - off] : 0;
        __syncthreads();
        sh[t] += v;
        __syncthreads();
    }
    int bb = (t > 0) ? sh[t - 1] : 0;
#pragma unroll
    for (int i = 0; i < per; i++) {
        int idx = base + i;
        if (idx < n) { int v = bb + loc[i]; g_rowstart[idx] = v; g_cursor[idx] = v; }
    }
    if (t == 1023) g_rowstart[n] = sh[1023];
}
__global__ void k_bucket(const int* __restrict__ ei) {
    int e = blockIdx.x * blockDim.x + threadIdx.x;
    if (e < NE) {
        int s = ei[e];
        int d = ei[NE + e];
        int pos = atomicAdd(&g_cursor[d], 1);
        g_srcs[pos] = s;
        g_ws[pos]   = -g_dinv[s] * g_dinv[d];
    }
}

// ---------------- GEMM1 via mma.sync TF32 (single product) -----------------
// Balanced flat partition (296 CTAs, 314 tiles of 64x128) + 2-stage cp.async.
// A in smem as raw fp32 [64 x 32k], pitch 144 (word 36m+k => 4m+k mod 32, CF).
// B in smem as raw fp32 [32k x 128n] straight from Wt, pitch 544 (8k+n, CF).
// Frags: ld.shared.f32 in m16n8k8 lane layout + cvt.rna.tf32. No conversions
// of A or B anywhere else; no convW pass.
#define APITCH   144
#define BPITCH   544
#define ABYTES   (64 * APITCH)          // 9216
#define STG      (ABYTES + 32 * BPITCH) // 9216 + 17408 = 26624
#define G1_SMEM  (2 * STG)

__global__ void __launch_bounds__(256, 2)
k_gemm1_mma(const float* __restrict__ X, const float* __restrict__ Wt,
            float* __restrict__ P) {
    extern __shared__ char smem[];
    const uint32_t sb = smem_u32(smem);
    const int tid  = threadIdx.x;
    const int wid  = tid >> 5, lane = tid & 31;
    const int warp_m = (wid >> 2) * 32;     // 2 m-warps
    const int warp_n = (wid & 3) * 32;      // 4 n-warps

    const int lq = lane >> 2;   // 0..7
    const int lr = lane & 3;    // 0..3

    float acc[2][4][4];

    long g  = (long)blockIdx.x * GWORK / NCTAS;
    long g1 = (long)(blockIdx.x + 1) * GWORK / NCTAS;

    while (g < g1) {
        const int t   = (int)(g / CH1);
        const int cst = (int)(g % CH1);
        int cend = CH1;
        {
            long avail = g1 - g;
            if ((long)(CH1 - cst) > avail) cend = cst + (int)avail;
        }
        const int m0  = (t >> 1) * 64;
        const int n0g = (t & 1) * 128;

#pragma unroll
        for (int i = 0; i < 2; i++)
#pragma unroll
            for (int j = 0; j < 4; j++)
#pragma unroll
                for (int q = 0; q < 4; q++) acc[i][j][q] = 0.0f;

#define ISSUE(c, st_) do {                                                       \
        int k0 = (c) * BKC;                                                      \
        uint32_t stg_ = sb + (uint32_t)(st_) * STG;                              \
        /* A: 64 rows x 32 floats = 512 x 16B, 2 per thread */                   \
        _Pragma("unroll")                                                        \
        for (int i_ = 0; i_ < 2; ++i_) {                                         \
            int u_ = tid * 2 + i_;                                               \
            int row_ = u_ >> 3, p_ = u_ & 7;                                     \
            const char* src_ = (const char*)(X + (size_t)(m0 + row_) * NN_NODES  \
                                             + k0 + p_ * 4);                     \
            uint32_t dst_ = stg_ + (uint32_t)(row_ * APITCH + p_ * 16);          \
            int sz_ = ((m0 + row_) < NN_NODES && (k0 + p_ * 4) < NN_NODES) ? 16 : 0; \
            CP16Z(dst_, src_, sz_);                                              \
        }                                                                        \
        /* B: 32 k-rows x 128 floats = 1024 x 16B, 4 per thread, from Wt */      \
        _Pragma("unroll")                                                        \
        for (int i_ = 0; i_ < 4; ++i_) {                                         \
            int u_ = tid * 4 + i_;                                               \
            int row_ = u_ >> 5, p_ = u_ & 31;                                    \
            const char* src_ = (const char*)(Wt + (size_t)(k0 + row_) * 256      \
                                             + n0g + p_ * 4);                    \
            uint32_t dst_ = stg_ + (uint32_t)ABYTES                              \
                            + (uint32_t)(row_ * BPITCH + p_ * 16);               \
            int sz_ = ((k0 + row_) < NN_NODES) ? 16 : 0;                         \
            CP16Z(dst_, src_, sz_);                                              \
        }                                                                        \
    } while (0)

        // prologue: issue stage 0
        ISSUE(cst, 0); CP_COMMIT();

        for (int c = cst; c < cend; ++c) {
            const int i = c - cst;
            CP_WAIT0();
            __syncthreads();
            if (c + 1 < cend) ISSUE(c + 1, (i + 1) & 1);
            CP_COMMIT();

            const uint32_t As = sb + (uint32_t)(i & 1) * STG;
            const uint32_t Bs = As + (uint32_t)ABYTES;
#pragma unroll
            for (int ks = 0; ks < 4; ++ks) {
                const int kc = ks * 8 + lr;
                uint32_t a[2][4], b[4][2];
#pragma unroll
                for (int mt = 0; mt < 2; ++mt) {
                    uint32_t ba = As + (uint32_t)((warp_m + mt * 16 + lq) * APITCH + kc * 4);
                    float x0, x1, x2, x3;
                    LDS32(x0, ba);
                    LDS32(x1, ba + 8u * APITCH);
                    LDS32(x2, ba + 16u);
                    LDS32(x3, ba + 8u * APITCH + 16u);
                    CVT_TF32(a[mt][0], x0); CVT_TF32(a[mt][1], x1);
                    CVT_TF32(a[mt][2], x2); CVT_TF32(a[mt][3], x3);
                }
#pragma unroll
                for (int nt = 0; nt < 4; ++nt) {
                    uint32_t bbselect = Bs + (uint32_t)(kc * BPITCH
                                       + (warp_n + nt * 8 + lq) * 4);
                    float y0, y1;
                    LDS32(y0, bbselect);
                    LDS32(y1, bbselect + 4u * BPITCH);
                    CVT_TF32(b[nt][0], y0); CVT_TF32(b[nt][1], y1);
                }
#pragma unroll
                for (int mt = 0; mt < 2; ++mt)
#pragma unroll
                    for (int nt = 0; nt < 4; ++nt)
                        mma16808(acc[mt][nt], a[mt], b[nt]);
            }
        }
#undef ISSUE

        // drain before reusing stages in the next segment
        CP_WAIT0();
        __syncthreads();

        // segment epilogue: accumulate partial into pre-zeroed P
        {
            const int gg = lane >> 2;
            const int t2 = (lane & 3) * 2;
#pragma unroll
            for (int nt = 0; nt < 4; ++nt) {
                int n = n0g + warp_n + nt * 8 + t2;
#pragma unroll
                for (int mt = 0; mt < 2; ++mt) {
                    int ma = m0 + warp_m + mt * 16 + gg;
                    if (ma < NN_NODES) {
                        atomicAdd(&P[(size_t)ma * 256 + n],     acc[mt][nt][0]);
                        atomicAdd(&P[(size_t)ma * 256 + n + 1], acc[mt][nt][1]);
                    }
                    int mb = ma + 8;
                    if (mb < NN_NODES) {
                        atomicAdd(&P[(size_t)mb * 256 + n],     acc[mt][nt][2]);
                        atomicAdd(&P[(size_t)mb * 256 + n + 1], acc[mt][nt][3]);
                    }
                }
            }
        }
        g += (long)(cend - cst);
    }
}

// h = relu(h + bias)  (in place)
__global__ void k_combine(const float* __restrict__ bt, float* __restrict__ H) {
    int i = blockIdx.x * blockDim.x + threadIdx.x;   // float4 index
    if (i < NN_NODES * IN_C / 4) {
        float4 a = reinterpret_cast<const float4*>(H)[i];
        int col = (i * 4) & 255;
        float4 o;
        o.x = fmaxf(a.x + bt[col + 0], 0.f);
        o.y = fmaxf(a.y + bt[col + 1], 0.f);
        o.z = fmaxf(a.z + bt[col + 2], 0.f);
        o.w = fmaxf(a.w + bt[col + 3], 0.f);
        reinterpret_cast<float4*>(H)[i] = o;
    }
}

// ---------------- SpMM: one block per dst row, one thread per channel -------
template <int CH>
__global__ void __launch_bounds__(CH) k_spmm(const float* __restrict__ h,
                                             float* __restrict__ tx) {
    int d = blockIdx.x;
    int c = threadIdx.x;
    int beg = g_rowstart[d];
    int end = g_rowstart[d + 1];
    float acc = 0.0f;
    int j = beg;
    for (; j + 4 <= end; j += 4) {
        int   s0 = g_srcs[j],   s1 = g_srcs[j+1], s2 = g_srcs[j+2], s3 = g_srcs[j+3];
        float w0 = g_ws[j],     w1 = g_ws[j+1],   w2 = g_ws[j+2],   w3 = g_ws[j+3];
        float h0 = h[(size_t)s0 * CH + c];
        float h1 = h[(size_t)s1 * CH + c];
        float h2 = h[(size_t)s2 * CH + c];
        float h3 = h[(size_t)s3 * CH + c];
        acc += w0 * h0; acc += w1 * h1; acc += w2 * h2; acc += w3 * h3;
    }
    for (; j < end; ++j)
        acc += g_ws[j] * h[(size_t)g_srcs[j] * CH + c];
    tx[(size_t)d * CH + c] = acc;
}

// ---------------- SIMT SGEMM for gemm2 --------------------------------------
template <int BM, int BN, int BK, int TM, int TN, bool RELU>
__global__ void __launch_bounds__((BM / TM) * (BN / TN))
k_gemm(const float* __restrict__ A1, const float* __restrict__ B1,
       const float* __restrict__ A2, const float* __restrict__ B2,
       const float* __restrict__ bias, float* __restrict__ C,
       int M, int N, int K) {
    constexpr int NT = (BM / TM) * (BN / TN);
    __shared__ float As[BK][BM];
    __shared__ float Bs[BK][BN];

    const int tid = threadIdx.x;
    const int m0 = blockIdx.y * BM;
    const int n0 = blockIdx.x * BN;
    const int tr = tid / (BN / TN);
    const int tc = tid % (BN / TN);
    const int rowBase = tr * TM;
    const int colBase = tc * TN;

    float acc[TM][TN];
#pragma unroll
    for (int i = 0; i < TM; i++)
#pragma unroll
        for (int j = 0; j < TN; j++) acc[i][j] = 0.0f;

    const int nphase = (A2 != nullptr) ? 2 : 1;
    for (int phase = 0; phase < nphase; ++phase) {
        const float* __restrict__ A = phase ? A2 : A1;
        const float* __restrict__ B = phase ? B2 : B1;
        for (int k0 = 0; k0 < K; k0 += BK) {
            constexpr int AIT = (BM * BK / 4) / NT;
#pragma unroll
            for (int it = 0; it < AIT; ++it) {
                int idx = tid + it * NT;
                int ar = idx / (BK / 4);
                int akg = idx % (BK / 4);
                int grow = m0 + ar;
                float4 f = make_float4(0.f, 0.f, 0.f, 0.f);
                if (grow < M)
                    f = *reinterpret_cast<const float4*>(A + (size_t)grow * K + k0 + akg * 4);
                As[akg * 4 + 0][ar] = f.x;
                As[akg * 4 + 1][ar] = f.y;
                As[akg * 4 + 2][ar] = f.z;
                As[akg * 4 + 3][ar] = f.w;
            }
            constexpr int BIT = (BK * BN) / NT;
#pragma unroll
            for (int it = 0; it < BIT; ++it) {
                int idx = tid + it * NT;
                int br = idx / BN;
                int bc = idx % BN;
                Bs[br][bc] = B[(size_t)(k0 + br) * N + n0 + bc];
            }
            __syncthreads();
#pragma unroll
            for (int k = 0; k < BK; k++) {
                float ra[TM], rb[TN];
#pragma unroll
                for (int i = 0; i < TM; i++) ra[i] = As[k][rowBase + i];
#pragma unroll
                for (int j = 0; j < TN; j++) rb[j] = Bs[k][colBase + j];
#pragma unroll
                for (int i = 0; i < TM; i++)
#pragma unroll
                    for (int j = 0; j < TN; j++)
                        acc[i][j] += ra[i] * rb[j];
            }
            __syncthreads();
        }
    }

    float bv[TN];
#pragma unroll
    for (int j = 0; j < TN; j++) bv[j] = bias[n0 + colBase + j];

#pragma unroll
    for (int i = 0; i < TM; i++) {
        int grow = m0 + rowBase + i;
        if (grow < M) {
            float4 o;
            float v0 = acc[i][0] + bv[0];
            float v1 = acc[i][1] + bv[1];
            float v2 = acc[i][2] + bv[2];
            float v3 = acc[i][3] + bv[3];
            if (RELU) {
                v0 = fmaxf(v0, 0.f); v1 = fmaxf(v1, 0.f);
                v2 = fmaxf(v2, 0.f); v3 = fmaxf(v3, 0.f);
            }
            o.x = v0; o.y = v1; o.z = v2; o.w = v3;
            *reinterpret_cast<float4*>(C + (size_t)grow * N + n0 + colBase) = o;
        }
    }
}

// ---------------- fused mu+logstd GEMM (shared A tiles) ---------------------
__global__ void __launch_bounds__(256)
k_gemm_dual(const float* __restrict__ A1, const float* __restrict__ A2,
            const float* __restrict__ Bm1, const float* __restrict__ Bm2,
            const float* __restrict__ Bl1, const float* __restrict__ Bl2,
            const float* __restrict__ bm, const float* __restrict__ bl,
            float* __restrict__ Cm, float* __restrict__ Cl) {
    __shared__ float As[8][64];
    __shared__ float Bmu[8][64];
    __shared__ float Bls[8][64];
    const int tid = threadIdx.x;
    const int m0 = blockIdx.x * 64;
    const int tr = tid >> 4, tc = tid & 15;

    float am[4][4], al_[4][4];
#pragma unroll
    for (int i = 0; i < 4; i++)
#pragma unroll
        for (int j = 0; j < 4; j++) { am[i][j] = 0.f; al_[i][j] = 0.f; }

    for (int ph = 0; ph < 2; ++ph) {
        const float* A   = ph ? A2  : A1;
        const float* Bm_ = ph ? Bm2 : Bm1;
        const float* Bl_ = ph ? Bl2 : Bl1;
        for (int k0 = 0; k0 < C1; k0 += 8) {
#pragma unroll
            for (int it = 0; it < 2; ++it) {
                int idx = tid + it * 256;
                int ar = idx >> 3, ak = idx & 7;
                int gm = m0 + ar;
                As[ak][ar] = (gm < NN_NODES) ? A[(size_t)gm * C1 + k0 + ak] : 0.f;
            }
#pragma unroll
            for (int it = 0; it < 2; ++it) {
                int idx = tid + it * 256;
                int bk = idx >> 6, bc = idx & 63;
                Bmu[bk][bc] = Bm_[(size_t)(k0 + bk) * 64 + bc];
                Bls[bk][bc] = Bl_[(size_t)(k0 + bk) * 64 + bc];
            }
            __syncthreads();
#pragma unroll
            for (int k = 0; k < 8; ++k) {
                float ra[4], rm[4], rl[4];
#pragma unroll
                for (int i = 0; i < 4; i++) {
                    ra[i] = As[k][tr * 4 + i];
                    rm[i] = Bmu[k][tc * 4 + i];
                    rl[i] = Bls[k][tc * 4 + i];
                }
#pragma unroll
                for (int i = 0; i < 4; i++)
#pragma unroll
                    for (int j = 0; j < 4; j++) {
                        am[i][j]  += ra[i] * rm[j];
                        al_[i][j] += ra[i] * rl[j];
                    }
            }
            __syncthreads();
        }
    }

    float bvm[4], bvl[4];
#pragma unroll
    for (int j = 0; j < 4; j++) { bvm[j] = bm[tc * 4 + j]; bvl[j] = bl[tc * 4 + j]; }
#pragma unroll
    for (int i = 0; i < 4; i++) {
        int gm = m0 + tr * 4 + i;
        if (gm < NN_NODES) {
            float4 om, ol;
            om.x = am[i][0] + bvm[0]; om.y = am[i][1] + bvm[1];
            om.z = am[i][2] + bvm[2]; om.w = am[i][3] + bvm[3];
            ol.x = al_[i][0] + bvl[0]; ol.y = al_[i][1] + bvl[1];
            ol.z = al_[i][2] + bvl[2]; ol.w = al_[i][3] + bvl[3];
            *reinterpret_cast<float4*>(Cm + (size_t)gm * 64 + tc * 4) = om;
            *reinterpret_cast<float4*>(Cl + (size_t)gm * 64 + tc * 4) = ol;
        }
    }
}

// ---------------- launcher --------------------------------------------------
extern "C" void kernel_launch(void* const* d_in, const int* in_sizes, int n_in,
                              void* d_out, int out_size) {
    const float* x    = (const float*)d_in[0];
    const int*   ei   = (const int*)d_in[1];
    const float* Wt   = (const float*)d_in[2];
    const float* bt   = (const float*)d_in[3];
    const float* W0_1 = (const float*)d_in[4];
    const float* W1_1 = (const float*)d_in[5];
    const float* b1   = (const float*)d_in[6];
    const float* W0mu = (const float*)d_in[7];
    const float* W1mu = (const float*)d_in[8];
    const float* bmu  = (const float*)d_in[9];
    const float* W0ls = (const float*)d_in[10];
    const float* W1ls = (const float*)d_in[11];
    const float* bls  = (const float*)d_in[12];
    float* out = (float*)d_out;

    float *h, *tx1, *h2, *tx2;
    cudaGetSymbolAddress((void**)&h,   g_h);
    cudaGetSymbolAddress((void**)&tx1, g_tx1);
    cudaGetSymbolAddress((void**)&h2,  g_h2);
    cudaGetSymbolAddress((void**)&tx2, g_tx2);

    cudaFuncSetAttribute(k_gemm1_mma, cudaFuncAttributeMaxDynamicSharedMemorySize, G1_SMEM);

    const int TPB = 256;

    // GEMM1 deps first; k_gemm1_mma stays at launch index 3 (ncu samples it)
    k_zeroH<<<(NN_NODES * IN_C / 4 + TPB - 1) / TPB, TPB>>>();       // 0
    k_zero_deg<<<(NN_NODES + TPB - 1) / TPB, TPB>>>(NN_NODES);       // 1
    k_count<<<(NE + TPB - 1) / TPB, TPB>>>(ei);                      // 2
    k_gemm1_mma<<<NCTAS, 256, G1_SMEM>>>(x, Wt, h);                  // 3
    k_combine<<<(NN_NODES * IN_C / 4 + TPB - 1) / TPB, TPB>>>(bt, h);
    k_dinv<<<(NN_NODES + TPB - 1) / TPB, TPB>>>(NN_NODES);
    k_scan<<<1, 1024>>>(NN_NODES);
    k_bucket<<<(NE + TPB - 1) / TPB, TPB>>>(ei);

    // tx1 = L_hat @ h
    k_spmm<IN_C><<<NN_NODES, IN_C>>>(h, tx1);

    // h2 = relu(h @ W0_1 + tx1 @ W1_1 + b1)
    {
        dim3 grid(C1 / 64, (NN_NODES + 127) / 128);
        k_gemm<128, 64, 8, 8, 4, true><<<grid, 256>>>(
            h, W0_1, tx1, W1_1, b1, h2, NN_NODES, C1, IN_C);
    }
    // tx2 = L_hat @ h2
    k_spmm<C1><<<NN_NODES, C1>>>(h2, tx2);

    // mu / logstd fused
    k_gemm_dual<<<157, 256>>>(h2, tx2, W0mu, W1mu, W0ls, W1ls,
                              bmu, bls, out, out + (size_t)NN_NODES * OUT_C);
}

// round 14
// speedup vs baseline: 1.1325x; 1.1325x over previous
#include <cuda_runtime.h>
#include <cuda_bf16.h>
#include <cstdint>
#include <cstddef>

// ---------------- problem constants ----------------
#define NN_NODES 10000
#define IN_C     256
#define C1       128
#define OUT_C    64
#define NE       640000
#define KPAD     10048          // padded K for B (zero-filled)
#define BKC      32             // K per mainloop chunk
#define CH1      313            // ceil(10000/32)
#define NTILES   158            // 79 m-blocks (128 rows) x 2 n-blocks (128 cols)
#define GWORK    ((long)NTILES * CH1)   // 49454 chunk-units
#define NCTAS    296            // 148 SMs x 2 CTAs/SM, one wave

// ---------------- PTX helpers ----------------
__device__ __forceinline__ uint32_t smem_u32(const void* p) {
    uint32_t a;
    asm("{ .reg .u64 t; cvta.to.shared.u64 t, %1; cvt.u32.u64 %0, t; }" : "=r"(a) : "l"(p));
    return a;
}
__device__ __forceinline__ void ldm_x4(uint32_t& r0, uint32_t& r1, uint32_t& r2, uint32_t& r3,
                                       uint32_t addr) {
    asm volatile("ldmatrix.sync.aligned.m8n8.x4.shared.b16 {%0,%1,%2,%3}, [%4];"
                 : "=r"(r0), "=r"(r1), "=r"(r2), "=r"(r3) : "r"(addr));
}
__device__ __forceinline__ void mma16816(float* d, const uint32_t* a, const uint32_t* b) {
    asm volatile("mma.sync.aligned.m16n8k16.row.col.f32.bf16.bf16.f32 "
                 "{%0,%1,%2,%3}, {%4,%5,%6,%7}, {%8,%9}, {%0,%1,%2,%3};"
                 : "+f"(d[0]), "+f"(d[1]), "+f"(d[2]), "+f"(d[3])
                 : "r"(a[0]), "r"(a[1]), "r"(a[2]), "r"(a[3]), "r"(b[0]), "r"(b[1]));
}
#define CP16(dst, src) \
    asm volatile("cp.async.cg.shared.global [%0], [%1], 16;" :: "r"(dst), "l"(src))
#define CP_COMMIT() asm volatile("cp.async.commit_group;")
#define CP_WAIT0()  asm volatile("cp.async.wait_group 0;")

// ---------------- scratch globals ----------------
__device__ float g_h   [NN_NODES * IN_C];   // zeroed, atomically accumulated, then final h
__device__ float g_tx1 [NN_NODES * IN_C];
__device__ float g_h2  [NN_NODES * C1];
__device__ float g_tx2 [NN_NODES * C1];
__device__ int   g_outdeg[NN_NODES];
__device__ int   g_indeg [NN_NODES];
__device__ float g_dinv  [NN_NODES];
__device__ int   g_rowstart[NN_NODES + 1];
__device__ int   g_cursor  [NN_NODES];
__device__ int   g_srcs [NE];
__device__ float g_ws   [NE];
__device__ __nv_bfloat16 g_BT_hi[256 * KPAD];   // Wt^T split-hi, [n][k]
__device__ __nv_bfloat16 g_BT_lo[256 * KPAD];   // Wt^T split-lo

// ---------------- preprocessing kernels ----------------
__global__ void k_zero_deg(int n) {
    int i = blockIdx.x * blockDim.x + threadIdx.x;
    if (i < n) { g_outdeg[i] = 0; g_indeg[i] = 0; }
}
__global__ void k_zeroH() {
    int i = blockIdx.x * blockDim.x + threadIdx.x;
    if (i < NN_NODES * IN_C / 4)
        reinterpret_cast<float4*>(g_h)[i] = make_float4(0.f, 0.f, 0.f, 0.f);
}
__global__ void k_count(const int* __restrict__ ei) {
    int e = blockIdx.x * blockDim.x + threadIdx.x;
    if (e < NE) {
        atomicAdd(&g_outdeg[ei[e]], 1);
        atomicAdd(&g_indeg[ei[NE + e]], 1);
    }
}
__global__ void k_dinv(int n) {
    int i = blockIdx.x * blockDim.x + threadIdx.x;
    if (i < n) {
        int d = g_outdeg[i];
        g_dinv[i] = (d > 0) ? rsqrtf((float)d) : 0.0f;
    }
}
// one-pass scan: each thread owns 10 rows
__global__ void k_scan(int n) {
    __shared__ int sh[1024];
    int t = threadIdx.x;
    const int per = 10;
    int base = t * per;
    int loc[10];
    int s = 0;
#pragma unroll
    for (int i = 0; i < per; i++) {
        int idx = base + i;
        int v = (idx < n) ? g_indeg[idx] : 0;
        loc[i] = s; s += v;
    }
    sh[t] = s;
    __syncthreads();
    for (int off = 1; off < 1024; off <<= 1) {
        int v = (t >= off) ? sh[t - off] : 0;
        __syncthreads();
        sh[t] += v;
        __syncthreads();
    }
    int bb = (t > 0) ? sh[t - 1] : 0;
#pragma unroll
    for (int i = 0; i < per; i++) {
        int idx = base + i;
        if (idx < n) { int v = bb + loc[i]; g_rowstart[idx] = v; g_cursor[idx] = v; }
    }
    if (t == 1023) g_rowstart[n] = sh[1023];
}
__global__ void k_bucket(const int* __restrict__ ei) {
    int e = blockIdx.x * blockDim.x + threadIdx.x;
    if (e < NE) {
        int s = ei[e];
        int d = ei[NE + e];
        int pos = atomicAdd(&g_cursor[d], 1);
        g_srcs[pos] = s;
        g_ws[pos]   = -g_dinv[s] * g_dinv[d];
    }
}

// Wt [10000,256] fp32 -> transposed bf16 hi/lo [256][KPAD]
__global__ void k_convW(const float* __restrict__ Wt) {
    __shared__ float tile[32][33];
    int bx = blockIdx.x, by = blockIdx.y;
    int tx = threadIdx.x, ty = threadIdx.y;
    int gk = bx * 32 + ty;
    int gn = by * 32 + tx;
    tile[ty][tx] = (gk < NN_NODES) ? Wt[(size_t)gk * 256 + gn] : 0.0f;
    __syncthreads();
    int n = by * 32 + ty;
    int k = bx * 32 + tx;
    float v = tile[tx][ty];
    __nv_bfloat16 hi = __float2bfloat16(v);
    __nv_bfloat16 lo = __float2bfloat16(v - __bfloat162float(hi));
    g_BT_hi[(size_t)n * KPAD + k] = hi;
    g_BT_lo[(size_t)n * KPAD + k] = lo;
}

// ---------------- GEMM1 via mma.sync bf16 (3-term split) --------------------
// R9 machinery with 128x128 CTA tile, warps 4m x 2n (warp tile 32x64).
// A: LDG fp32 -> register split -> STS bf16 hi/lo (proven path, pitch 80B).
// B: pre-split bf16 via cp.async (unchanged from R9). BK=32, 2-stage,
// flat balanced partition over 158 tiles x 313 chunks on 296 CTAs.
// Stage: Ahi@0 (128x80), Alo@10240, Bhi@20480, Blo@30720 -> 40960 B.
#define G1_STG   40960
#define G1_SMEM  (2 * G1_STG)
#define PITCH    80

__global__ void __launch_bounds__(256, 2)
k_gemm1_mma(const float* __restrict__ X, float* __restrict__ P) {
    extern __shared__ char smem[];
    const uint32_t sb = smem_u32(smem);
    const int tid  = threadIdx.x;
    const int wid  = tid >> 5, lane = tid & 31;
    const int warp_m = (wid >> 1) * 32;     // 4 m-warps
    const int warp_n = (wid & 1) * 64;      // 2 n-warps

    // A loader coords: 128 rows x 2 threads/row, 16 floats each
    const int alr = tid >> 1;
    const int alq = tid & 1;
    // B loader coords: 128 rows x 2 threads/row
    const int blr = tid >> 1;
    const int blh = tid & 1;

    // ldmatrix lane offsets
    const int La     = lane & 7;
    const int a_moff = ((lane >> 3) & 1) * 8 + La;
    const int a_koff = (lane >> 4) * 8;
    const int b_noff = (lane >> 4) * 8 + La;
    const int b_koff = ((lane >> 3) & 1) * 8;

    const char* bhsrc = (const char*)g_BT_hi;
    const char* blsrc = (const char*)g_BT_lo;
    const size_t brow = (size_t)KPAD * 2;

    float4 v[4];
    float acc[2][8][4];

    long g  = (long)blockIdx.x * GWORK / NCTAS;
    long g1 = (long)(blockIdx.x + 1) * GWORK / NCTAS;

    while (g < g1) {
        const int t   = (int)(g / CH1);
        const int cst = (int)(g % CH1);
        int cend = CH1;
        {
            long avail = g1 - g;
            if ((long)(CH1 - cst) > avail) cend = cst + (int)avail;
        }
        const int m0  = (t >> 1) * 128;
        const int n0g = (t & 1) * 128;

#pragma unroll
        for (int i = 0; i < 2; i++)
#pragma unroll
            for (int j = 0; j < 8; j++)
#pragma unroll
                for (int q = 0; q < 4; q++) acc[i][j][q] = 0.0f;

#define LDG_A(c) do {                                                           \
        int k0 = (c) * BKC;                                                     \
        int grow = m0 + alr;                                                    \
        _Pragma("unroll")                                                       \
        for (int i = 0; i < 4; i++) {                                           \
            int gk = k0 + alq * 16 + i * 4;                                     \
            v[i] = (grow < NN_NODES && gk < NN_NODES)                           \
                 ? *reinterpret_cast<const float4*>(X + (size_t)grow * NN_NODES + gk) \
                 : make_float4(0.f, 0.f, 0.f, 0.f);                             \
        }                                                                       \
    } while (0)

#define CPA_B(c, st) do {                                                       \
        int k0 = (c) * BKC;                                                     \
        uint32_t dsth = sb + (st) * G1_STG + 20480 + blr * PITCH + blh * 32;    \
        const char* sh_ = bhsrc + (size_t)(n0g + blr) * brow + k0 * 2 + blh * 32; \
        const char* sl_ = blsrc + (size_t)(n0g + blr) * brow + k0 * 2 + blh * 32; \
        CP16(dsth,       sh_);      CP16(dsth + 16,         sh_ + 16);          \
        CP16(dsth+10240, sl_);      CP16(dsth + 10240 + 16, sl_ + 16);          \
        CP_COMMIT();                                                            \
    } while (0)

#define STS_A(st) do {                                                          \
        uint32_t dh = sb + (st) * G1_STG + alr * PITCH + alq * 32;              \
        uint32_t hA[8], lA[8];                                                  \
        _Pragma("unroll")                                                       \
        for (int i = 0; i < 4; i++) {                                           \
            __nv_bfloat16 h0 = __float2bfloat16(v[i].x);                        \
            __nv_bfloat16 h1 = __float2bfloat16(v[i].y);                        \
            __nv_bfloat16 h2 = __float2bfloat16(v[i].z);                        \
            __nv_bfloat16 h3 = __float2bfloat16(v[i].w);                        \
            __nv_bfloat16 l0 = __float2bfloat16(v[i].x - __bfloat162float(h0)); \
            __nv_bfloat16 l1 = __float2bfloat16(v[i].y - __bfloat162float(h1)); \
            __nv_bfloat16 l2 = __float2bfloat16(v[i].z - __bfloat162float(h2)); \
            __nv_bfloat16 l3 = __float2bfloat16(v[i].w - __bfloat162float(h3)); \
            hA[i*2+0] = (uint32_t)__bfloat16_as_ushort(h0) | ((uint32_t)__bfloat16_as_ushort(h1) << 16); \
            hA[i*2+1] = (uint32_t)__bfloat16_as_ushort(h2) | ((uint32_t)__bfloat16_as_ushort(h3) << 16); \
            lA[i*2+0] = (uint32_t)__bfloat16_as_ushort(l0) | ((uint32_t)__bfloat16_as_ushort(l1) << 16); \
            lA[i*2+1] = (uint32_t)__bfloat16_as_ushort(l2) | ((uint32_t)__bfloat16_as_ushort(l3) << 16); \
        }                                                                       \
        asm volatile("st.shared.v4.b32 [%0], {%1,%2,%3,%4};"                    \
            :: "r"(dh), "r"(hA[0]), "r"(hA[1]), "r"(hA[2]), "r"(hA[3]));        \
        asm volatile("st.shared.v4.b32 [%0], {%1,%2,%3,%4};"                    \
            :: "r"(dh + 16), "r"(hA[4]), "r"(hA[5]), "r"(hA[6]), "r"(hA[7]));   \
        asm volatile("st.shared.v4.b32 [%0], {%1,%2,%3,%4};"                    \
            :: "r"(dh + 10240), "r"(lA[0]), "r"(lA[1]), "r"(lA[2]), "r"(lA[3]));\
        asm volatile("st.shared.v4.b32 [%0], {%1,%2,%3,%4};"                    \
            :: "r"(dh + 10240 + 16), "r"(lA[4]), "r"(lA[5]), "r"(lA[6]), "r"(lA[7])); \
    } while (0)

        // segment prologue: fill stage 0 with chunk cst
        LDG_A(cst);
        CPA_B(cst, 0);
        STS_A(0);
        CP_WAIT0();
        __syncthreads();

        for (int c = cst; c < cend; ++c) {
            const int st  = (c - cst) & 1;
            const int nst = st ^ 1;
            const bool pre = (c + 1 < cend);
            if (pre) { LDG_A(c + 1); CPA_B(c + 1, nst); }

            const uint32_t abase = sb + st * G1_STG;
            const uint32_t bbase = abase + 20480;
#pragma unroll
            for (int ks = 0; ks < 2; ++ks) {
                const int kb = ks * 16;
                uint32_t ah[2][4], al[2][4];
#pragma unroll
                for (int mt = 0; mt < 2; ++mt) {
                    uint32_t ra = abase + (uint32_t)((warp_m + mt * 16 + a_moff) * PITCH + (kb + a_koff) * 2);
                    ldm_x4(ah[mt][0], ah[mt][1], ah[mt][2], ah[mt][3], ra);
                    ldm_x4(al[mt][0], al[mt][1], al[mt][2], al[mt][3], ra + 10240);
                }
                // stream B per 16-col group to cap registers
#pragma unroll
                for (int bb = 0; bb < 4; ++bb) {
                    uint32_t bh[4], bl[4];
                    uint32_t rb = bbase + (uint32_t)((warp_n + bb * 16 + b_noff) * PITCH + (kb + b_koff) * 2);
                    ldm_x4(bh[0], bh[1], bh[2], bh[3], rb);
                    ldm_x4(bl[0], bl[1], bl[2], bl[3], rb + 10240);
#pragma unroll
                    for (int mt = 0; mt < 2; ++mt)
#pragma unroll
                        for (int hf = 0; hf < 2; ++hf) {
                            int nt = bb * 2 + hf;
                            mma16816(acc[mt][nt], ah[mt], &bh[hf * 2]);
                            mma16816(acc[mt][nt], ah[mt], &bl[hf * 2]);
                            mma16816(acc[mt][nt], al[mt], &bh[hf * 2]);
                        }
                }
            }

            if (pre) { STS_A(nst); CP_WAIT0(); }
            __syncthreads();
        }
#undef LDG_A
#undef CPA_B
#undef STS_A

        // segment epilogue: accumulate partial into pre-zeroed P
        {
            const int gg = lane >> 2;
            const int t2 = (lane & 3) * 2;
#pragma unroll
            for (int nt = 0; nt < 8; ++nt) {
                int n = n0g + warp_n + nt * 8 + t2;
#pragma unroll
                for (int mt = 0; mt < 2; ++mt) {
                    int ma = m0 + warp_m + mt * 16 + gg;
                    if (ma < NN_NODES) {
                        atomicAdd(&P[(size_t)ma * 256 + n],     acc[mt][nt][0]);
                        atomicAdd(&P[(size_t)ma * 256 + n + 1], acc[mt][nt][1]);
                    }
                    int mb = ma + 8;
                    if (mb < NN_NODES) {
                        atomicAdd(&P[(size_t)mb * 256 + n],     acc[mt][nt][2]);
                        atomicAdd(&P[(size_t)mb * 256 + n + 1], acc[mt][nt][3]);
                    }
                }
            }
        }
        g += (long)(cend - cst);
    }
}

// h = relu(h + bias)  (in place)
__global__ void k_combine(const float* __restrict__ bt, float* __restrict__ H) {
    int i = blockIdx.x * blockDim.x + threadIdx.x;   // float4 index
    if (i < NN_NODES * IN_C / 4) {
        float4 a = reinterpret_cast<const float4*>(H)[i];
        int col = (i * 4) & 255;
        float4 o;
        o.x = fmaxf(a.x + bt[col + 0], 0.f);
        o.y = fmaxf(a.y + bt[col + 1], 0.f);
        o.z = fmaxf(a.z + bt[col + 2], 0.f);
        o.w = fmaxf(a.w + bt[col + 3], 0.f);
        reinterpret_cast<float4*>(H)[i] = o;
    }
}

// ---------------- SpMM: one block per dst row, one thread per channel -------
template <int CH>
__global__ void __launch_bounds__(CH) k_spmm(const float* __restrict__ h,
                                             float* __restrict__ tx) {
    int d = blockIdx.x;
    int c = threadIdx.x;
    int beg = g_rowstart[d];
    int end = g_rowstart[d + 1];
    float acc = 0.0f;
    int j = beg;
    for (; j + 4 <= end; j += 4) {
        int   s0 = g_srcs[j],   s1 = g_srcs[j+1], s2 = g_srcs[j+2], s3 = g_srcs[j+3];
        float w0 = g_ws[j],     w1 = g_ws[j+1],   w2 = g_ws[j+2],   w3 = g_ws[j+3];
        float h0 = h[(size_t)s0 * CH + c];
        float h1 = h[(size_t)s1 * CH + c];
        float h2 = h[(size_t)s2 * CH + c];
        float h3 = h[(size_t)s3 * CH + c];
        acc += w0 * h0; acc += w1 * h1; acc += w2 * h2; acc += w3 * h3;
    }
    for (; j < end; ++j)
        acc += g_ws[j] * h[(size_t)g_srcs[j] * CH + c];
    tx[(size_t)d * CH + c] = acc;
}

// ---------------- SIMT SGEMM for gemm2 --------------------------------------
template <int BM, int BN, int BK, int TM, int TN, bool RELU>
__global__ void __launch_bounds__((BM / TM) * (BN / TN))
k_gemm(const float* __restrict__ A1, const float* __restrict__ B1,
       const float* __restrict__ A2, const float* __restrict__ B2,
       const float* __restrict__ bias, float* __restrict__ C,
       int M, int N, int K) {
    constexpr int NT = (BM / TM) * (BN / TN);
    __shared__ float As[BK][BM];
    __shared__ float Bs[BK][BN];

    const int tid = threadIdx.x;
    const int m0 = blockIdx.y * BM;
    const int n0 = blockIdx.x * BN;
    const int tr = tid / (BN / TN);
    const int tc = tid % (BN / TN);
    const int rowBase = tr * TM;
    const int colBase = tc * TN;

    float acc[TM][TN];
#pragma unroll
    for (int i = 0; i < TM; i++)
#pragma unroll
        for (int j = 0; j < TN; j++) acc[i][j] = 0.0f;

    const int nphase = (A2 != nullptr) ? 2 : 1;
    for (int phase = 0; phase < nphase; ++phase) {
        const float* __restrict__ A = phase ? A2 : A1;
        const float* __restrict__ B = phase ? B2 : B1;
        for (int k0 = 0; k0 < K; k0 += BK) {
            constexpr int AIT = (BM * BK / 4) / NT;
#pragma unroll
            for (int it = 0; it < AIT; ++it) {
                int idx = tid + it * NT;
                int ar = idx / (BK / 4);
                int akg = idx % (BK / 4);
                int grow = m0 + ar;
                float4 f = make_float4(0.f, 0.f, 0.f, 0.f);
                if (grow < M)
                    f = *reinterpret_cast<const float4*>(A + (size_t)grow * K + k0 + akg * 4);
                As[akg * 4 + 0][ar] = f.x;
                As[akg * 4 + 1][ar] = f.y;
                As[akg * 4 + 2][ar] = f.z;
                As[akg * 4 + 3][ar] = f.w;
            }
            constexpr int BIT = (BK * BN) / NT;
#pragma unroll
            for (int it = 0; it < BIT; ++it) {
                int idx = tid + it * NT;
                int br = idx / BN;
                int bc = idx % BN;
                Bs[br][bc] = B[(size_t)(k0 + br) * N + n0 + bc];
            }
            __syncthreads();
#pragma unroll
            for (int k = 0; k < BK; k++) {
                float ra[TM], rb[TN];
#pragma unroll
                for (int i = 0; i < TM; i++) ra[i] = As[k][rowBase + i];
#pragma unroll
                for (int j = 0; j < TN; j++) rb[j] = Bs[k][colBase + j];
#pragma unroll
                for (int i = 0; i < TM; i++)
#pragma unroll
                    for (int j = 0; j < TN; j++)
                        acc[i][j] += ra[i] * rb[j];
            }
            __syncthreads();
        }
    }

    float bv[TN];
#pragma unroll
    for (int j = 0; j < TN; j++) bv[j] = bias[n0 + colBase + j];

#pragma unroll
    for (int i = 0; i < TM; i++) {
        int grow = m0 + rowBase + i;
        if (grow < M) {
            float4 o;
            float v0 = acc[i][0] + bv[0];
            float v1 = acc[i][1] + bv[1];
            float v2 = acc[i][2] + bv[2];
            float v3 = acc[i][3] + bv[3];
            if (RELU) {
                v0 = fmaxf(v0, 0.f); v1 = fmaxf(v1, 0.f);
                v2 = fmaxf(v2, 0.f); v3 = fmaxf(v3, 0.f);
            }
            o.x = v0; o.y = v1; o.z = v2; o.w = v3;
            *reinterpret_cast<float4*>(C + (size_t)grow * N + n0 + colBase) = o;
        }
    }
}

// ---------------- fused mu+logstd GEMM (shared A tiles) ---------------------
__global__ void __launch_bounds__(256)
k_gemm_dual(const float* __restrict__ A1, const float* __restrict__ A2,
            const float* __restrict__ Bm1, const float* __restrict__ Bm2,
            const float* __restrict__ Bl1, const float* __restrict__ Bl2,
            const float* __restrict__ bm, const float* __restrict__ bl,
            float* __restrict__ Cm, float* __restrict__ Cl) {
    __shared__ float As[8][64];
    __shared__ float Bmu[8][64];
    __shared__ float Bls[8][64];
    const int tid = threadIdx.x;
    const int m0 = blockIdx.x * 64;
    const int tr = tid >> 4, tc = tid & 15;

    float am[4][4], al_[4][4];
#pragma unroll
    for (int i = 0; i < 4; i++)
#pragma unroll
        for (int j = 0; j < 4; j++) { am[i][j] = 0.f; al_[i][j] = 0.f; }

    for (int ph = 0; ph < 2; ++ph) {
        const float* A   = ph ? A2  : A1;
        const float* Bm_ = ph ? Bm2 : Bm1;
        const float* Bl_ = ph ? Bl2 : Bl1;
        for (int k0 = 0; k0 < C1; k0 += 8) {
#pragma unroll
            for (int it = 0; it < 2; ++it) {
                int idx = tid + it * 256;
                int ar = idx >> 3, ak = idx & 7;
                int gm = m0 + ar;
                As[ak][ar] = (gm < NN_NODES) ? A[(size_t)gm * C1 + k0 + ak] : 0.f;
            }
#pragma unroll
            for (int it = 0; it < 2; ++it) {
                int idx = tid + it * 256;
                int bk = idx >> 6, bc = idx & 63;
                Bmu[bk][bc] = Bm_[(size_t)(k0 + bk) * 64 + bc];
                Bls[bk][bc] = Bl_[(size_t)(k0 + bk) * 64 + bc];
            }
            __syncthreads();
#pragma unroll
            for (int k = 0; k < 8; ++k) {
                float ra[4], rm[4], rl[4];
#pragma unroll
                for (int i = 0; i < 4; i++) {
                    ra[i] = As[k][tr * 4 + i];
                    rm[i] = Bmu[k][tc * 4 + i];
                    rl[i] = Bls[k][tc * 4 + i];
                }
#pragma unroll
                for (int i = 0; i < 4; i++)
#pragma unroll
                    for (int j = 0; j < 4; j++) {
                        am[i][j]  += ra[i] * rm[j];
                        al_[i][j] += ra[i] * rl[j];
                    }
            }
            __syncthreads();
        }
    }

    float bvm[4], bvl[4];
#pragma unroll
    for (int j = 0; j < 4; j++) { bvm[j] = bm[tc * 4 + j]; bvl[j] = bl[tc * 4 + j]; }
#pragma unroll
    for (int i = 0; i < 4; i++) {
        int gm = m0 + tr * 4 + i;
        if (gm < NN_NODES) {
            float4 om, ol;
            om.x = am[i][0] + bvm[0]; om.y = am[i][1] + bvm[1];
            om.z = am[i][2] + bvm[2]; om.w = am[i][3] + bvm[3];
            ol.x = al_[i][0] + bvl[0]; ol.y = al_[i][1] + bvl[1];
            ol.z = al_[i][2] + bvl[2]; ol.w = al_[i][3] + bvl[3];
            *reinterpret_cast<float4*>(Cm + (size_t)gm * 64 + tc * 4) = om;
            *reinterpret_cast<float4*>(Cl + (size_t)gm * 64 + tc * 4) = ol;
        }
    }
}

// ---------------- launcher --------------------------------------------------
extern "C" void kernel_launch(void* const* d_in, const int* in_sizes, int n_in,
                              void* d_out, int out_size) {
    const float* x    = (const float*)d_in[0];
    const int*   ei   = (const int*)d_in[1];
    const float* Wt   = (const float*)d_in[2];
    const float* bt   = (const float*)d_in[3];
    const float* W0_1 = (const float*)d_in[4];
    const float* W1_1 = (const float*)d_in[5];
    const float* b1   = (const float*)d_in[6];
    const float* W0mu = (const float*)d_in[7];
    const float* W1mu = (const float*)d_in[8];
    const float* bmu  = (const float*)d_in[9];
    const float* W0ls = (const float*)d_in[10];
    const float* W1ls = (const float*)d_in[11];
    const float* bls  = (const float*)d_in[12];
    float* out = (float*)d_out;

    float *h, *tx1, *h2, *tx2;
    cudaGetSymbolAddress((void**)&h,   g_h);
    cudaGetSymbolAddress((void**)&tx1, g_tx1);
    cudaGetSymbolAddress((void**)&h2,  g_h2);
    cudaGetSymbolAddress((void**)&tx2, g_tx2);

    cudaFuncSetAttribute(k_gemm1_mma, cudaFuncAttributeMaxDynamicSharedMemorySize, G1_SMEM);

    const int TPB = 256;

    // GEMM1 deps first; k_gemm1_mma stays at launch index 3 (ncu samples it)
    {
        dim3 grid(KPAD / 32, 256 / 32), blk(32, 32);
        k_convW<<<grid, blk>>>(Wt);                                  // 0
    }
    k_zeroH<<<(NN_NODES * IN_C / 4 + TPB - 1) / TPB, TPB>>>();       // 1
    k_zero_deg<<<(NN_NODES + TPB - 1) / TPB, TPB>>>(NN_NODES);       // 2
    k_gemm1_mma<<<NCTAS, 256, G1_SMEM>>>(x, h);                      // 3
    k_combine<<<(NN_NODES * IN_C / 4 + TPB - 1) / TPB, TPB>>>(bt, h);
    k_count<<<(NE + TPB - 1) / TPB, TPB>>>(ei);
    k_dinv<<<(NN_NODES + TPB - 1) / TPB, TPB>>>(NN_NODES);
    k_scan<<<1, 1024>>>(NN_NODES);
    k_bucket<<<(NE + TPB - 1) / TPB, TPB>>>(ei);

    // tx1 = L_hat @ h
    k_spmm<IN_C><<<NN_NODES, IN_C>>>(h, tx1);

    // h2 = relu(h @ W0_1 + tx1 @ W1_1 + b1)
    {
        dim3 grid(C1 / 64, (NN_NODES + 127) / 128);
        k_gemm<128, 64, 8, 8, 4, true><<<grid, 256>>>(
            h, W0_1, tx1, W1_1, b1, h2, NN_NODES, C1, IN_C);
    }
    // tx2 = L_hat @ h2
    k_spmm<C1><<<NN_NODES, C1>>>(h2, tx2);

    // mu / logstd fused
    k_gemm_dual<<<157, 256>>>(h2, tx2, W0mu, W1mu, W0ls, W1ls,
                              bmu, bls, out, out + (size_t)NN_NODES * OUT_C);
}

// round 15
// speedup vs baseline: 1.4799x; 1.3068x over previous
#include <cuda_runtime.h>
#include <cuda_fp16.h>
#include <cstdint>
#include <cstddef>

// ---------------- problem constants ----------------
#define NN_NODES 10000
#define IN_C     256
#define C1       128
#define OUT_C    64
#define NE       640000
#define KPAD     10048          // padded K for B (zero-filled)
#define BKC      32             // K per mainloop chunk
#define CH1      313            // ceil(10000/32)
#define NTILES   158            // 79 m-blocks (128 rows) x 2 n-blocks (128 cols)
#define GWORK    ((long)NTILES * CH1)   // 49454 chunk-units
#define NCTAS    296            // 148 SMs x 2 CTAs/SM, one wave

// ---------------- PTX helpers ----------------
__device__ __forceinline__ uint32_t smem_u32(const void* p) {
    uint32_t a;
    asm("{ .reg .u64 t; cvta.to.shared.u64 t, %1; cvt.u32.u64 %0, t; }" : "=r"(a) : "l"(p));
    return a;
}
__device__ __forceinline__ void ldm_x4(uint32_t& r0, uint32_t& r1, uint32_t& r2, uint32_t& r3,
                                       uint32_t addr) {
    asm volatile("ldmatrix.sync.aligned.m8n8.x4.shared.b16 {%0,%1,%2,%3}, [%4];"
                 : "=r"(r0), "=r"(r1), "=r"(r2), "=r"(r3) : "r"(addr));
}
__device__ __forceinline__ void mma16816h(float* d, const uint32_t* a, const uint32_t* b) {
    asm volatile("mma.sync.aligned.m16n8k16.row.col.f32.f16.f16.f32 "
                 "{%0,%1,%2,%3}, {%4,%5,%6,%7}, {%8,%9}, {%0,%1,%2,%3};"
                 : "+f"(d[0]), "+f"(d[1]), "+f"(d[2]), "+f"(d[3])
                 : "r"(a[0]), "r"(a[1]), "r"(a[2]), "r"(a[3]), "r"(b[0]), "r"(b[1]));
}
#define CP16(dst, src) \
    asm volatile("cp.async.cg.shared.global [%0], [%1], 16;" :: "r"(dst), "l"(src))
#define CP_COMMIT() asm volatile("cp.async.commit_group;")
#define CP_WAIT0()  asm volatile("cp.async.wait_group 0;")

// ---------------- scratch globals ----------------
__device__ float g_h   [NN_NODES * IN_C];   // zeroed, atomically accumulated, then final h
__device__ float g_tx1 [NN_NODES * IN_C];
__device__ float g_h2  [NN_NODES * C1];
__device__ float g_tx2 [NN_NODES * C1];
__device__ int   g_outdeg[NN_NODES];
__device__ int   g_indeg [NN_NODES];
__device__ float g_dinv  [NN_NODES];
__device__ int   g_rowstart[NN_NODES + 1];
__device__ int   g_cursor  [NN_NODES];
__device__ int   g_srcs [NE];
__device__ float g_ws   [NE];
__device__ __half g_BTh[256 * KPAD];        // Wt^T as fp16, [n][k]

// ---------------- preprocessing kernels ----------------
__global__ void k_zero_deg(int n) {
    int i = blockIdx.x * blockDim.x + threadIdx.x;
    if (i < n) { g_outdeg[i] = 0; g_indeg[i] = 0; }
}
__global__ void k_zeroH() {
    int i = blockIdx.x * blockDim.x + threadIdx.x;
    if (i < NN_NODES * IN_C / 4)
        reinterpret_cast<float4*>(g_h)[i] = make_float4(0.f, 0.f, 0.f, 0.f);
}
__global__ void k_count(const int* __restrict__ ei) {
    int e = blockIdx.x * blockDim.x + threadIdx.x;
    if (e < NE) {
        atomicAdd(&g_outdeg[ei[e]], 1);
        atomicAdd(&g_indeg[ei[NE + e]], 1);
    }
}
__global__ void k_dinv(int n) {
    int i = blockIdx.x * blockDim.x + threadIdx.x;
    if (i < n) {
        int d = g_outdeg[i];
        g_dinv[i] = (d > 0) ? rsqrtf((float)d) : 0.0f;
    }
}
// one-pass scan: each thread owns 10 rows
__global__ void k_scan(int n) {
    __shared__ int sh[1024];
    int t = threadIdx.x;
    const int per = 10;
    int base = t * per;
    int loc[10];
    int s = 0;
#pragma unroll
    for (int i = 0; i < per; i++) {
        int idx = base + i;
        int v = (idx < n) ? g_indeg[idx] : 0;
        loc[i] = s; s += v;
    }
    sh[t] = s;
    __syncthreads();
    for (int off = 1; off < 1024; off <<= 1) {
        int v = (t >= off) ? sh[t - off] : 0;
        __syncthreads();
        sh[t] += v;
        __syncthreads();
    }
    int bb = (t > 0) ? sh[t - 1] : 0;
#pragma unroll
    for (int i = 0; i < per; i++) {
        int idx = base + i;
        if (idx < n) { int v = bb + loc[i]; g_rowstart[idx] = v; g_cursor[idx] = v; }
    }
    if (t == 1023) g_rowstart[n] = sh[1023];
}
__global__ void k_bucket(const int* __restrict__ ei) {
    int e = blockIdx.x * blockDim.x + threadIdx.x;
    if (e < NE) {
        int s = ei[e];
        int d = ei[NE + e];
        int pos = atomicAdd(&g_cursor[d], 1);
        g_srcs[pos] = s;
        g_ws[pos]   = -g_dinv[s] * g_dinv[d];
    }
}

// Wt [10000,256] fp32 -> transposed fp16 [256][KPAD]
__global__ void k_convW(const float* __restrict__ Wt) {
    __shared__ float tile[32][33];
    int bx = blockIdx.x, by = blockIdx.y;
    int tx = threadIdx.x, ty = threadIdx.y;
    int gk = bx * 32 + ty;
    int gn = by * 32 + tx;
    tile[ty][tx] = (gk < NN_NODES) ? Wt[(size_t)gk * 256 + gn] : 0.0f;
    __syncthreads();
    int n = by * 32 + ty;
    int k = bx * 32 + tx;
    g_BTh[(size_t)n * KPAD + k] = __float2half(tile[tx][ty]);
}

// ---------------- GEMM1 via mma.sync FP16 (single product) ------------------
// R13 machinery minus the lo planes. CTA 128x128, warps 4m x 2n (tile 32x64).
// A: LDG fp32 -> cvt fp16 -> STS (pitch 80B). B: fp16 via cp.async.
// BK=32, 2-stage, flat balanced partition (158 tiles x 313 chunks, 296 CTAs).
// Stage: A@0 (128x80=10240) | B@10240 (128x80) -> 20480 B.
#define G1_STG   20480
#define G1_SMEM  (2 * G1_STG)
#define PITCH    80

__global__ void __launch_bounds__(256, 2)
k_gemm1_mma(const float* __restrict__ X, float* __restrict__ P) {
    extern __shared__ char smem[];
    const uint32_t sb = smem_u32(smem);
    const int tid  = threadIdx.x;
    const int wid  = tid >> 5, lane = tid & 31;
    const int warp_m = (wid >> 1) * 32;     // 4 m-warps
    const int warp_n = (wid & 1) * 64;      // 2 n-warps

    // A loader coords: 128 rows x 2 threads/row, 16 floats each
    const int alr = tid >> 1;
    const int alq = tid & 1;
    // B loader coords: 128 rows x 2 threads/row, 32B each
    const int blr = tid >> 1;
    const int blh = tid & 1;

    // ldmatrix lane offsets
    const int La     = lane & 7;
    const int a_moff = ((lane >> 3) & 1) * 8 + La;
    const int a_koff = (lane >> 4) * 8;
    const int b_noff = (lane >> 4) * 8 + La;
    const int b_koff = ((lane >> 3) & 1) * 8;

    const char* bsrc = (const char*)g_BTh;
    const size_t brow = (size_t)KPAD * 2;

    float4 v[4];
    float acc[2][8][4];

    long g  = (long)blockIdx.x * GWORK / NCTAS;
    long g1 = (long)(blockIdx.x + 1) * GWORK / NCTAS;

    while (g < g1) {
        const int t   = (int)(g / CH1);
        const int cst = (int)(g % CH1);
        int cend = CH1;
        {
            long avail = g1 - g;
            if ((long)(CH1 - cst) > avail) cend = cst + (int)avail;
        }
        const int m0  = (t >> 1) * 128;
        const int n0g = (t & 1) * 128;

#pragma unroll
        for (int i = 0; i < 2; i++)
#pragma unroll
            for (int j = 0; j < 8; j++)
#pragma unroll
                for (int q = 0; q < 4; q++) acc[i][j][q] = 0.0f;

#define LDG_A(c) do {                                                           \
        int k0 = (c) * BKC;                                                     \
        int grow = m0 + alr;                                                    \
        _Pragma("unroll")                                                       \
        for (int i = 0; i < 4; i++) {                                           \
            int gk = k0 + alq * 16 + i * 4;                                     \
            v[i] = (grow < NN_NODES && gk < NN_NODES)                           \
                 ? *reinterpret_cast<const float4*>(X + (size_t)grow * NN_NODES + gk) \
                 : make_float4(0.f, 0.f, 0.f, 0.f);                             \
        }                                                                       \
    } while (0)

#define CPA_B(c, st) do {                                                       \
        int k0 = (c) * BKC;                                                     \
        uint32_t dsth = sb + (st) * G1_STG + 10240 + blr * PITCH + blh * 32;    \
        const char* sh_ = bsrc + (size_t)(n0g + blr) * brow + k0 * 2 + blh * 32; \
        CP16(dsth, sh_);  CP16(dsth + 16, sh_ + 16);                            \
        CP_COMMIT();                                                            \
    } while (0)

#define STS_A(st) do {                                                          \
        uint32_t dh = sb + (st) * G1_STG + alr * PITCH + alq * 32;              \
        uint32_t hA[8];                                                         \
        _Pragma("unroll")                                                       \
        for (int i = 0; i < 4; i++) {                                           \
            __half h0 = __float2half(v[i].x);                                   \
            __half h1 = __float2half(v[i].y);                                   \
            __half h2 = __float2half(v[i].z);                                   \
            __half h3 = __float2half(v[i].w);                                   \
            hA[i*2+0] = (uint32_t)__half_as_ushort(h0) | ((uint32_t)__half_as_ushort(h1) << 16); \
            hA[i*2+1] = (uint32_t)__half_as_ushort(h2) | ((uint32_t)__half_as_ushort(h3) << 16); \
        }                                                                       \
        asm volatile("st.shared.v4.b32 [%0], {%1,%2,%3,%4};"                    \
            :: "r"(dh), "r"(hA[0]), "r"(hA[1]), "r"(hA[2]), "r"(hA[3]));        \
        asm volatile("st.shared.v4.b32 [%0], {%1,%2,%3,%4};"                    \
            :: "r"(dh + 16), "r"(hA[4]), "r"(hA[5]), "r"(hA[6]), "r"(hA[7]));   \
    } while (0)

        // segment prologue: fill stage 0 with chunk cst
        LDG_A(cst);
        CPA_B(cst, 0);
        STS_A(0);
        CP_WAIT0();
        __syncthreads();

        for (int c = cst; c < cend; ++c) {
            const int st  = (c - cst) & 1;
            const int nst = st ^ 1;
            const bool pre = (c + 1 < cend);
            if (pre) { LDG_A(c + 1); CPA_B(c + 1, nst); }

            const uint32_t abase = sb + st * G1_STG;
            const uint32_t bbase = abase + 10240;
#pragma unroll
            for (int ks = 0; ks < 2; ++ks) {
                const int kb = ks * 16;
                uint32_t ah[2][4];
#pragma unroll
                for (int mt = 0; mt < 2; ++mt) {
                    uint32_t ra = abase + (uint32_t)((warp_m + mt * 16 + a_moff) * PITCH + (kb + a_koff) * 2);
                    ldm_x4(ah[mt][0], ah[mt][1], ah[mt][2], ah[mt][3], ra);
                }
                // stream B per 16-col group
#pragma unroll
                for (int bb = 0; bb < 4; ++bb) {
                    uint32_t bh[4];
                    uint32_t rb = bbase + (uint32_t)((warp_n + bb * 16 + b_noff) * PITCH + (kb + b_koff) * 2);
                    ldm_x4(bh[0], bh[1], bh[2], bh[3], rb);
#pragma unroll
                    for (int mt = 0; mt < 2; ++mt)
#pragma unroll
                        for (int hf = 0; hf < 2; ++hf)
                            mma16816h(acc[mt][bb * 2 + hf], ah[mt], &bh[hf * 2]);
                }
            }

            if (pre) { STS_A(nst); CP_WAIT0(); }
            __syncthreads();
        }
#undef LDG_A
#undef CPA_B
#undef STS_A

        // segment epilogue: accumulate partial into pre-zeroed P
        {
            const int gg = lane >> 2;
            const int t2 = (lane & 3) * 2;
#pragma unroll
            for (int nt = 0; nt < 8; ++nt) {
                int n = n0g + warp_n + nt * 8 + t2;
#pragma unroll
                for (int mt = 0; mt < 2; ++mt) {
                    int ma = m0 + warp_m + mt * 16 + gg;
                    if (ma < NN_NODES) {
                        atomicAdd(&P[(size_t)ma * 256 + n],     acc[mt][nt][0]);
                        atomicAdd(&P[(size_t)ma * 256 + n + 1], acc[mt][nt][1]);
                    }
                    int mb = ma + 8;
                    if (mb < NN_NODES) {
                        atomicAdd(&P[(size_t)mb * 256 + n],     acc[mt][nt][2]);
                        atomicAdd(&P[(size_t)mb * 256 + n + 1], acc[mt][nt][3]);
                    }
                }
            }
        }
        g += (long)(cend - cst);
    }
}

// h = relu(h + bias)  (in place)
__global__ void k_combine(const float* __restrict__ bt, float* __restrict__ H) {
    int i = blockIdx.x * blockDim.x + threadIdx.x;   // float4 index
    if (i < NN_NODES * IN_C / 4) {
        float4 a = reinterpret_cast<const float4*>(H)[i];
        int col = (i * 4) & 255;
        float4 o;
        o.x = fmaxf(a.x + bt[col + 0], 0.f);
        o.y = fmaxf(a.y + bt[col + 1], 0.f);
        o.z = fmaxf(a.z + bt[col + 2], 0.f);
        o.w = fmaxf(a.w + bt[col + 3], 0.f);
        reinterpret_cast<float4*>(H)[i] = o;
    }
}

// ---------------- SpMM: one block per dst row, one thread per channel -------
template <int CH>
__global__ void __launch_bounds__(CH) k_spmm(const float* __restrict__ h,
                                             float* __restrict__ tx) {
    int d = blockIdx.x;
    int c = threadIdx.x;
    int beg = g_rowstart[d];
    int end = g_rowstart[d + 1];
    float acc = 0.0f;
    int j = beg;
    for (; j + 4 <= end; j += 4) {
        int   s0 = g_srcs[j],   s1 = g_srcs[j+1], s2 = g_srcs[j+2], s3 = g_srcs[j+3];
        float w0 = g_ws[j],     w1 = g_ws[j+1],   w2 = g_ws[j+2],   w3 = g_ws[j+3];
        float h0 = h[(size_t)s0 * CH + c];
        float h1 = h[(size_t)s1 * CH + c];
        float h2 = h[(size_t)s2 * CH + c];
        float h3 = h[(size_t)s3 * CH + c];
        acc += w0 * h0; acc += w1 * h1; acc += w2 * h2; acc += w3 * h3;
    }
    for (; j < end; ++j)
        acc += g_ws[j] * h[(size_t)g_srcs[j] * CH + c];
    tx[(size_t)d * CH + c] = acc;
}

// ---------------- SIMT SGEMM for gemm2 --------------------------------------
template <int BM, int BN, int BK, int TM, int TN, bool RELU>
__global__ void __launch_bounds__((BM / TM) * (BN / TN))
k_gemm(const float* __restrict__ A1, const float* __restrict__ B1,
       const float* __restrict__ A2, const float* __restrict__ B2,
       const float* __restrict__ bias, float* __restrict__ C,
       int M, int N, int K) {
    constexpr int NT = (BM / TM) * (BN / TN);
    __shared__ float As[BK][BM];
    __shared__ float Bs[BK][BN];

    const int tid = threadIdx.x;
    const int m0 = blockIdx.y * BM;
    const int n0 = blockIdx.x * BN;
    const int tr = tid / (BN / TN);
    const int tc = tid % (BN / TN);
    const int rowBase = tr * TM;
    const int colBase = tc * TN;

    float acc[TM][TN];
#pragma unroll
    for (int i = 0; i < TM; i++)
#pragma unroll
        for (int j = 0; j < TN; j++) acc[i][j] = 0.0f;

    const int nphase = (A2 != nullptr) ? 2 : 1;
    for (int phase = 0; phase < nphase; ++phase) {
        const float* __restrict__ A = phase ? A2 : A1;
        const float* __restrict__ B = phase ? B2 : B1;
        for (int k0 = 0; k0 < K; k0 += BK) {
            constexpr int AIT = (BM * BK / 4) / NT;
#pragma unroll
            for (int it = 0; it < AIT; ++it) {
                int idx = tid + it * NT;
                int ar = idx / (BK / 4);
                int akg = idx % (BK / 4);
                int grow = m0 + ar;
                float4 f = make_float4(0.f, 0.f, 0.f, 0.f);
                if (grow < M)
                    f = *reinterpret_cast<const float4*>(A + (size_t)grow * K + k0 + akg * 4);
                As[akg * 4 + 0][ar] = f.x;
                As[akg * 4 + 1][ar] = f.y;
                As[akg * 4 + 2][ar] = f.z;
                As[akg * 4 + 3][ar] = f.w;
            }
            constexpr int BIT = (BK * BN) / NT;
#pragma unroll
            for (int it = 0; it < BIT; ++it) {
                int idx = tid + it * NT;
                int br = idx / BN;
                int bc = idx % BN;
                Bs[br][bc] = B[(size_t)(k0 + br) * N + n0 + bc];
            }
            __syncthreads();
#pragma unroll
            for (int k = 0; k < BK; k++) {
                float ra[TM], rb[TN];
#pragma unroll
                for (int i = 0; i < TM; i++) ra[i] = As[k][rowBase + i];
#pragma unroll
                for (int j = 0; j < TN; j++) rb[j] = Bs[k][colBase + j];
#pragma unroll
                for (int i = 0; i < TM; i++)
#pragma unroll
                    for (int j = 0; j < TN; j++)
                        acc[i][j] += ra[i] * rb[j];
            }
            __syncthreads();
        }
    }

    float bv[TN];
#pragma unroll
    for (int j = 0; j < TN; j++) bv[j] = bias[n0 + colBase + j];

#pragma unroll
    for (int i = 0; i < TM; i++) {
        int grow = m0 + rowBase + i;
        if (grow < M) {
            float4 o;
            float v0 = acc[i][0] + bv[0];
            float v1 = acc[i][1] + bv[1];
            float v2 = acc[i][2] + bv[2];
            float v3 = acc[i][3] + bv[3];
            if (RELU) {
                v0 = fmaxf(v0, 0.f); v1 = fmaxf(v1, 0.f);
                v2 = fmaxf(v2, 0.f); v3 = fmaxf(v3, 0.f);
            }
            o.x = v0; o.y = v1; o.z = v2; o.w = v3;
            *reinterpret_cast<float4*>(C + (size_t)grow * N + n0 + colBase) = o;
        }
    }
}

// ---------------- fused mu+logstd GEMM (shared A tiles) ---------------------
__global__ void __launch_bounds__(256)
k_gemm_dual(const float* __restrict__ A1, const float* __restrict__ A2,
            const float* __restrict__ Bm1, const float* __restrict__ Bm2,
            const float* __restrict__ Bl1, const float* __restrict__ Bl2,
            const float* __restrict__ bm, const float* __restrict__ bl,
            float* __restrict__ Cm, float* __restrict__ Cl) {
    __shared__ float As[8][64];
    __shared__ float Bmu[8][64];
    __shared__ float Bls[8][64];
    const int tid = threadIdx.x;
    const int m0 = blockIdx.x * 64;
    const int tr = tid >> 4, tc = tid & 15;

    float am[4][4], al_[4][4];
#pragma unroll
    for (int i = 0; i < 4; i++)
#pragma unroll
        for (int j = 0; j < 4; j++) { am[i][j] = 0.f; al_[i][j] = 0.f; }

    for (int ph = 0; ph < 2; ++ph) {
        const float* A   = ph ? A2  : A1;
        const float* Bm_ = ph ? Bm2 : Bm1;
        const float* Bl_ = ph ? Bl2 : Bl1;
        for (int k0 = 0; k0 < C1; k0 += 8) {
#pragma unroll
            for (int it = 0; it < 2; ++it) {
                int idx = tid + it * 256;
                int ar = idx >> 3, ak = idx & 7;
                int gm = m0 + ar;
                As[ak][ar] = (gm < NN_NODES) ? A[(size_t)gm * C1 + k0 + ak] : 0.f;
            }
#pragma unroll
            for (int it = 0; it < 2; ++it) {
                int idx = tid + it * 256;
                int bk = idx >> 6, bc = idx & 63;
                Bmu[bk][bc] = Bm_[(size_t)(k0 + bk) * 64 + bc];
                Bls[bk][bc] = Bl_[(size_t)(k0 + bk) * 64 + bc];
            }
            __syncthreads();
#pragma unroll
            for (int k = 0; k < 8; ++k) {
                float ra[4], rm[4], rl[4];
#pragma unroll
                for (int i = 0; i < 4; i++) {
                    ra[i] = As[k][tr * 4 + i];
                    rm[i] = Bmu[k][tc * 4 + i];
                    rl[i] = Bls[k][tc * 4 + i];
                }
#pragma unroll
                for (int i = 0; i < 4; i++)
#pragma unroll
                    for (int j = 0; j < 4; j++) {
                        am[i][j]  += ra[i] * rm[j];
                        al_[i][j] += ra[i] * rl[j];
                    }
            }
            __syncthreads();
        }
    }

    float bvm[4], bvl[4];
#pragma unroll
    for (int j = 0; j < 4; j++) { bvm[j] = bm[tc * 4 + j]; bvl[j] = bl[tc * 4 + j]; }
#pragma unroll
    for (int i = 0; i < 4; i++) {
        int gm = m0 + tr * 4 + i;
        if (gm < NN_NODES) {
            float4 om, ol;
            om.x = am[i][0] + bvm[0]; om.y = am[i][1] + bvm[1];
            om.z = am[i][2] + bvm[2]; om.w = am[i][3] + bvm[3];
            ol.x = al_[i][0] + bvl[0]; ol.y = al_[i][1] + bvl[1];
            ol.z = al_[i][2] + bvl[2]; ol.w = al_[i][3] + bvl[3];
            *reinterpret_cast<float4*>(Cm + (size_t)gm * 64 + tc * 4) = om;
            *reinterpret_cast<float4*>(Cl + (size_t)gm * 64 + tc * 4) = ol;
        }
    }
}

// ---------------- launcher --------------------------------------------------
extern "C" void kernel_launch(void* const* d_in, const int* in_sizes, int n_in,
                              void* d_out, int out_size) {
    const float* x    = (const float*)d_in[0];
    const int*   ei   = (const int*)d_in[1];
    const float* Wt   = (const float*)d_in[2];
    const float* bt   = (const float*)d_in[3];
    const float* W0_1 = (const float*)d_in[4];
    const float* W1_1 = (const float*)d_in[5];
    const float* b1   = (const float*)d_in[6];
    const float* W0mu = (const float*)d_in[7];
    const float* W1mu = (const float*)d_in[8];
    const float* bmu  = (const float*)d_in[9];
    const float* W0ls = (const float*)d_in[10];
    const float* W1ls = (const float*)d_in[11];
    const float* bls  = (const float*)d_in[12];
    float* out = (float*)d_out;

    float *h, *tx1, *h2, *tx2;
    cudaGetSymbolAddress((void**)&h,   g_h);
    cudaGetSymbolAddress((void**)&tx1, g_tx1);
    cudaGetSymbolAddress((void**)&h2,  g_h2);
    cudaGetSymbolAddress((void**)&tx2, g_tx2);

    cudaFuncSetAttribute(k_gemm1_mma, cudaFuncAttributeMaxDynamicSharedMemorySize, G1_SMEM);

    const int TPB = 256;

    // GEMM1 deps first; k_gemm1_mma stays at launch index 3 (ncu samples it)
    {
        dim3 grid(KPAD / 32, 256 / 32), blk(32, 32);
        k_convW<<<grid, blk>>>(Wt);                                  // 0
    }
    k_zeroH<<<(NN_NODES * IN_C / 4 + TPB - 1) / TPB, TPB>>>();       // 1
    k_zero_deg<<<(NN_NODES + TPB - 1) / TPB, TPB>>>(NN_NODES);       // 2
    k_gemm1_mma<<<NCTAS, 256, G1_SMEM>>>(x, h);                      // 3
    k_combine<<<(NN_NODES * IN_C / 4 + TPB - 1) / TPB, TPB>>>(bt, h);
    k_count<<<(NE + TPB - 1) / TPB, TPB>>>(ei);
    k_dinv<<<(NN_NODES + TPB - 1) / TPB, TPB>>>(NN_NODES);
    k_scan<<<1, 1024>>>(NN_NODES);
    k_bucket<<<(NE + TPB - 1) / TPB, TPB>>>(ei);

    // tx1 = L_hat @ h
    k_spmm<IN_C><<<NN_NODES, IN_C>>>(h, tx1);

    // h2 = relu(h @ W0_1 + tx1 @ W1_1 + b1)
    {
        dim3 grid(C1 / 64, (NN_NODES + 127) / 128);
        k_gemm<128, 64, 8, 8, 4, true><<<grid, 256>>>(
            h, W0_1, tx1, W1_1, b1, h2, NN_NODES, C1, IN_C);
    }
    // tx2 = L_hat @ h2
    k_spmm<C1><<<NN_NODES, C1>>>(h2, tx2);

    // mu / logstd fused
    k_gemm_dual<<<157, 256>>>(h2, tx2, W0mu, W1mu, W0ls, W1ls,
                              bmu, bls, out, out + (size_t)NN_NODES * OUT_C);
}

// round 16
// speedup vs baseline: 1.8940x; 1.2799x over previous
#include <cuda_runtime.h>
#include <cuda_fp16.h>
#include <cstdint>
#include <cstddef>

// ---------------- problem constants ----------------
#define NN_NODES 10000
#define IN_C     256
#define C1       128
#define OUT_C    64
#define NE       640000
#define KPAD     10048          // padded K for B (zero-filled)
#define BKC      32             // K per mainloop chunk
#define CH1      313            // ceil(10000/32)
#define NTILES   158            // 79 m-blocks (128 rows) x 2 n-blocks (128 cols)
#define GWORK    ((long)NTILES * CH1)
#define NCTAS    296            // 148 SMs x 2 CTAs/SM, one wave
#define MB79     79             // ceil(10000/128)

// ---------------- PTX helpers ----------------
__device__ __forceinline__ uint32_t smem_u32(const void* p) {
    uint32_t a;
    asm("{ .reg .u64 t; cvta.to.shared.u64 t, %1; cvt.u32.u64 %0, t; }" : "=r"(a) : "l"(p));
    return a;
}
__device__ __forceinline__ void ldm_x4(uint32_t& r0, uint32_t& r1, uint32_t& r2, uint32_t& r3,
                                       uint32_t addr) {
    asm volatile("ldmatrix.sync.aligned.m8n8.x4.shared.b16 {%0,%1,%2,%3}, [%4];"
                 : "=r"(r0), "=r"(r1), "=r"(r2), "=r"(r3) : "r"(addr));
}
__device__ __forceinline__ void mma16816h(float* d, const uint32_t* a, const uint32_t* b) {
    asm volatile("mma.sync.aligned.m16n8k16.row.col.f32.f16.f16.f32 "
                 "{%0,%1,%2,%3}, {%4,%5,%6,%7}, {%8,%9}, {%0,%1,%2,%3};"
                 : "+f"(d[0]), "+f"(d[1]), "+f"(d[2]), "+f"(d[3])
                 : "r"(a[0]), "r"(a[1]), "r"(a[2]), "r"(a[3]), "r"(b[0]), "r"(b[1]));
}
#define CP16(dst, src) \
    asm volatile("cp.async.cg.shared.global [%0], [%1], 16;" :: "r"(dst), "l"(src))
#define CP16Z(dst, src, sz) \
    asm volatile("cp.async.cg.shared.global [%0], [%1], 16, %2;" :: "r"(dst), "l"(src), "r"(sz))
#define CP_COMMIT() asm volatile("cp.async.commit_group;")
#define CP_WAIT0()  asm volatile("cp.async.wait_group 0;")

// ---------------- scratch globals ----------------
__device__ float  g_h   [NN_NODES * IN_C];       // fp32 atomic accum for GEMM1
__device__ __half g_h16 [NN_NODES * IN_C];       // h as fp16
__device__ __half g_tx116[NN_NODES * IN_C];      // tx1 fp16
__device__ __half g_h216[NN_NODES * C1];         // h2 fp16
__device__ __half g_tx216[NN_NODES * C1];        // tx2 fp16
__device__ int   g_outdeg[NN_NODES];
__device__ int   g_indeg [NN_NODES];
__device__ float g_dinv  [NN_NODES];
__device__ int   g_rowstart[NN_NODES + 1];
__device__ int   g_cursor  [NN_NODES];
__device__ int   g_srcs [NE];
__device__ float g_ws   [NE];
__device__ __half g_BTh[256 * KPAD];             // Wt^T fp16 [n][k]
__device__ __half g_W2h[2 * 128 * 256];          // {W0_1,W1_1}^T fp16 [ph][n][k]
__device__ __half g_Wdh[2 * 128 * 128];          // {[Wmu;Wls]}^T fp16 [ph][n][k]

// ---------------- preprocessing kernels ----------------
__global__ void k_zero_deg(int n) {
    int i = blockIdx.x * blockDim.x + threadIdx.x;
    if (i < n) { g_outdeg[i] = 0; g_indeg[i] = 0; }
}
__global__ void k_zeroH() {
    int i = blockIdx.x * blockDim.x + threadIdx.x;
    if (i < NN_NODES * IN_C / 4)
        reinterpret_cast<float4*>(g_h)[i] = make_float4(0.f, 0.f, 0.f, 0.f);
}
__global__ void k_count(const int* __restrict__ ei) {
    int e = blockIdx.x * blockDim.x + threadIdx.x;
    if (e < NE) {
        atomicAdd(&g_outdeg[ei[e]], 1);
        atomicAdd(&g_indeg[ei[NE + e]], 1);
    }
}
__global__ void k_dinv(int n) {
    int i = blockIdx.x * blockDim.x + threadIdx.x;
    if (i < n) {
        int d = g_outdeg[i];
        g_dinv[i] = (d > 0) ? rsqrtf((float)d) : 0.0f;
    }
}
__global__ void k_scan(int n) {
    __shared__ int sh[1024];
    int t = threadIdx.x;
    const int per = 10;
    int base = t * per;
    int loc[10];
    int s = 0;
#pragma unroll
    for (int i = 0; i < per; i++) {
        int idx = base + i;
        int v = (idx < n) ? g_indeg[idx] : 0;
        loc[i] = s; s += v;
    }
    sh[t] = s;
    __syncthreads();
    for (int off = 1; off < 1024; off <<= 1) {
        int v = (t >= off) ? sh[t - off] : 0;
        __syncthreads();
        sh[t] += v;
        __syncthreads();
    }
    int bb = (t > 0) ? sh[t - 1] : 0;
#pragma unroll
    for (int i = 0; i < per; i++) {
        int idx = base + i;
        if (idx < n) { int v = bb + loc[i]; g_rowstart[idx] = v; g_cursor[idx] = v; }
    }
    if (t == 1023) g_rowstart[n] = sh[1023];
}
__global__ void k_bucket(const int* __restrict__ ei) {
    int e = blockIdx.x * blockDim.x + threadIdx.x;
    if (e < NE) {
        int s = ei[e];
        int d = ei[NE + e];
        int pos = atomicAdd(&g_cursor[d], 1);
        g_srcs[pos] = s;
        g_ws[pos]   = -g_dinv[s] * g_dinv[d];
    }
}

// Wt [10000,256] fp32 -> transposed fp16 [256][KPAD]
__global__ void k_convW(const float* __restrict__ Wt) {
    __shared__ float tile[32][33];
    int bx = blockIdx.x, by = blockIdx.y;
    int tx = threadIdx.x, ty = threadIdx.y;
    int gk = bx * 32 + ty;
    int gn = by * 32 + tx;
    tile[ty][tx] = (gk < NN_NODES) ? Wt[(size_t)gk * 256 + gn] : 0.0f;
    __syncthreads();
    int n = by * 32 + ty;
    int k = bx * 32 + tx;
    g_BTh[(size_t)n * KPAD + k] = __float2half(tile[tx][ty]);
}

// W0_1/W1_1 [256,128] -> g_W2h[ph][n(128)][k(256)] fp16
__global__ void k_convW2(const float* __restrict__ W0, const float* __restrict__ W1) {
    __shared__ float tile[32][33];
    int ph = blockIdx.z;
    const float* W = ph ? W1 : W0;
    int k0 = blockIdx.x * 32, n0 = blockIdx.y * 32;
    int tx = threadIdx.x, ty = threadIdx.y;
    tile[ty][tx] = W[(size_t)(k0 + ty) * 128 + n0 + tx];
    __syncthreads();
    g_W2h[(size_t)ph * 128 * 256 + (size_t)(n0 + ty) * 256 + k0 + tx] =
        __float2half(tile[tx][ty]);
}

// Wmu/Wls [128,64] -> g_Wdh[ph][n(128: 0-63 mu,64-127 ls)][k(128)] fp16
__global__ void k_convWd(const float* __restrict__ W0m, const float* __restrict__ W1m,
                         const float* __restrict__ W0l, const float* __restrict__ W1l) {
    __shared__ float tile[32][33];
    int ph = blockIdx.z;
    int nb = blockIdx.y;                 // 0..3
    const float* W = (nb < 2) ? (ph ? W1m : W0m) : (ph ? W1l : W0l);
    int k0 = blockIdx.x * 32;
    int nc0 = (nb & 1) * 32;             // col within the 64
    int tx = threadIdx.x, ty = threadIdx.y;
    tile[ty][tx] = W[(size_t)(k0 + ty) * 64 + nc0 + tx];
    __syncthreads();
    g_Wdh[(size_t)ph * 128 * 128 + (size_t)(nb * 32 + ty) * 128 + k0 + tx] =
        __float2half(tile[tx][ty]);
}

// ---------------- GEMM1 via mma.sync FP16 (unchanged from R14) --------------
#define G1_STG   20480
#define G1_SMEM  (2 * G1_STG)
#define PITCH    80

__global__ void __launch_bounds__(256, 2)
k_gemm1_mma(const float* __restrict__ X, float* __restrict__ P) {
    extern __shared__ char smem[];
    const uint32_t sb = smem_u32(smem);
    const int tid  = threadIdx.x;
    const int wid  = tid >> 5, lane = tid & 31;
    const int warp_m = (wid >> 1) * 32;
    const int warp_n = (wid & 1) * 64;

    const int alr = tid >> 1;
    const int alq = tid & 1;
    const int blr = tid >> 1;
    const int blh = tid & 1;

    const int La     = lane & 7;
    const int a_moff = ((lane >> 3) & 1) * 8 + La;
    const int a_koff = (lane >> 4) * 8;
    const int b_noff = (lane >> 4) * 8 + La;
    const int b_koff = ((lane >> 3) & 1) * 8;

    const char* bsrc = (const char*)g_BTh;
    const size_t brow = (size_t)KPAD * 2;

    float4 v[4];
    float acc[2][8][4];

    long g  = (long)blockIdx.x * GWORK / NCTAS;
    long g1 = (long)(blockIdx.x + 1) * GWORK / NCTAS;

    while (g < g1) {
        const int t   = (int)(g / CH1);
        const int cst = (int)(g % CH1);
        int cend = CH1;
        {
            long avail = g1 - g;
            if ((long)(CH1 - cst) > avail) cend = cst + (int)avail;
        }
        const int m0  = (t >> 1) * 128;
        const int n0g = (t & 1) * 128;

#pragma unroll
        for (int i = 0; i < 2; i++)
#pragma unroll
            for (int j = 0; j < 8; j++)
#pragma unroll
                for (int q = 0; q < 4; q++) acc[i][j][q] = 0.0f;

#define LDG_A(c) do {                                                           \
        int k0 = (c) * BKC;                                                     \
        int grow = m0 + alr;                                                    \
        _Pragma("unroll")                                                       \
        for (int i = 0; i < 4; i++) {                                           \
            int gk = k0 + alq * 16 + i * 4;                                     \
            v[i] = (grow < NN_NODES && gk < NN_NODES)                           \
                 ? *reinterpret_cast<const float4*>(X + (size_t)grow * NN_NODES + gk) \
                 : make_float4(0.f, 0.f, 0.f, 0.f);                             \
        }                                                                       \
    } while (0)

#define CPA_B(c, st) do {                                                       \
        int k0 = (c) * BKC;                                                     \
        uint32_t dsth = sb + (st) * G1_STG + 10240 + blr * PITCH + blh * 32;    \
        const char* sh_ = bsrc + (size_t)(n0g + blr) * brow + k0 * 2 + blh * 32; \
        CP16(dsth, sh_);  CP16(dsth + 16, sh_ + 16);                            \
        CP_COMMIT();                                                            \
    } while (0)

#define STS_A(st) do {                                                          \
        uint32_t dh = sb + (st) * G1_STG + alr * PITCH + alq * 32;              \
        uint32_t hA[8];                                                         \
        _Pragma("unroll")                                                       \
        for (int i = 0; i < 4; i++) {                                           \
            __half h0 = __float2half(v[i].x);                                   \
            __half h1 = __float2half(v[i].y);                                   \
            __half h2 = __float2half(v[i].z);                                   \
            __half h3 = __float2half(v[i].w);                                   \
            hA[i*2+0] = (uint32_t)__half_as_ushort(h0) | ((uint32_t)__half_as_ushort(h1) << 16); \
            hA[i*2+1] = (uint32_t)__half_as_ushort(h2) | ((uint32_t)__half_as_ushort(h3) << 16); \
        }                                                                       \
        asm volatile("st.shared.v4.b32 [%0], {%1,%2,%3,%4};"                    \
            :: "r"(dh), "r"(hA[0]), "r"(hA[1]), "r"(hA[2]), "r"(hA[3]));        \
        asm volatile("st.shared.v4.b32 [%0], {%1,%2,%3,%4};"                    \
            :: "r"(dh + 16), "r"(hA[4]), "r"(hA[5]), "r"(hA[6]), "r"(hA[7]));   \
    } while (0)

        LDG_A(cst);
        CPA_B(cst, 0);
        STS_A(0);
        CP_WAIT0();
        __syncthreads();

        for (int c = cst; c < cend; ++c) {
            const int st  = (c - cst) & 1;
            const int nst = st ^ 1;
            const bool pre = (c + 1 < cend);
            if (pre) { LDG_A(c + 1); CPA_B(c + 1, nst); }

            const uint32_t abase = sb + st * G1_STG;
            const uint32_t bbase = abase + 10240;
#pragma unroll
            for (int ks = 0; ks < 2; ++ks) {
                const int kb = ks * 16;
                uint32_t ah[2][4];
#pragma unroll
                for (int mt = 0; mt < 2; ++mt) {
                    uint32_t ra = abase + (uint32_t)((warp_m + mt * 16 + a_moff) * PITCH + (kb + a_koff) * 2);
                    ldm_x4(ah[mt][0], ah[mt][1], ah[mt][2], ah[mt][3], ra);
                }
#pragma unroll
                for (int bb = 0; bb < 4; ++bb) {
                    uint32_t bh[4];
                    uint32_t rb = bbase + (uint32_t)((warp_n + bb * 16 + b_noff) * PITCH + (kb + b_koff) * 2);
                    ldm_x4(bh[0], bh[1], bh[2], bh[3], rb);
#pragma unroll
                    for (int mt = 0; mt < 2; ++mt)
#pragma unroll
                        for (int hf = 0; hf < 2; ++hf)
                            mma16816h(acc[mt][bb * 2 + hf], ah[mt], &bh[hf * 2]);
                }
            }

            if (pre) { STS_A(nst); CP_WAIT0(); }
            __syncthreads();
        }
#undef LDG_A
#undef CPA_B
#undef STS_A

        {
            const int gg = lane >> 2;
            const int t2 = (lane & 3) * 2;
#pragma unroll
            for (int nt = 0; nt < 8; ++nt) {
                int n = n0g + warp_n + nt * 8 + t2;
#pragma unroll
                for (int mt = 0; mt < 2; ++mt) {
                    int ma = m0 + warp_m + mt * 16 + gg;
                    if (ma < NN_NODES) {
                        atomicAdd(&P[(size_t)ma * 256 + n],     acc[mt][nt][0]);
                        atomicAdd(&P[(size_t)ma * 256 + n + 1], acc[mt][nt][1]);
                    }
                    int mb = ma + 8;
                    if (mb < NN_NODES) {
                        atomicAdd(&P[(size_t)mb * 256 + n],     acc[mt][nt][2]);
                        atomicAdd(&P[(size_t)mb * 256 + n + 1], acc[mt][nt][3]);
                    }
                }
            }
        }
        g += (long)(cend - cst);
    }
}

// h16 = fp16(relu(h + bias))
__global__ void k_combine(const float* __restrict__ bt, const float* __restrict__ Hf,
                          __half* __restrict__ H16) {
    int i = blockIdx.x * blockDim.x + threadIdx.x;   // float4 index
    if (i < NN_NODES * IN_C / 4) {
        float4 a = reinterpret_cast<const float4*>(Hf)[i];
        int col = (i * 4) & 255;
        float v0 = fmaxf(a.x + bt[col + 0], 0.f);
        float v1 = fmaxf(a.y + bt[col + 1], 0.f);
        float v2 = fmaxf(a.z + bt[col + 2], 0.f);
        float v3 = fmaxf(a.w + bt[col + 3], 0.f);
        __half2* p = reinterpret_cast<__half2*>(H16);
        p[i * 2 + 0] = __floats2half2_rn(v0, v1);
        p[i * 2 + 1] = __floats2half2_rn(v2, v3);
    }
}

// ---------------- SpMM fp16: block per dst row, thread per half2 channel ----
template <int CH>
__global__ void __launch_bounds__(CH / 2) k_spmm_h(const __half* __restrict__ h,
                                                   __half* __restrict__ tx) {
    int d = blockIdx.x;
    int c = threadIdx.x;                     // half2 channel
    const __half2* hp = reinterpret_cast<const __half2*>(h);
    int beg = g_rowstart[d];
    int end = g_rowstart[d + 1];
    float ax = 0.f, ay = 0.f;
    int j = beg;
    for (; j + 4 <= end; j += 4) {
        int   s0 = g_srcs[j],   s1 = g_srcs[j+1], s2 = g_srcs[j+2], s3 = g_srcs[j+3];
        float w0 = g_ws[j],     w1 = g_ws[j+1],   w2 = g_ws[j+2],   w3 = g_ws[j+3];
        float2 f0 = __half22float2(hp[(size_t)s0 * (CH/2) + c]);
        float2 f1 = __half22float2(hp[(size_t)s1 * (CH/2) + c]);
        float2 f2 = __half22float2(hp[(size_t)s2 * (CH/2) + c]);
        float2 f3 = __half22float2(hp[(size_t)s3 * (CH/2) + c]);
        ax += w0 * f0.x + w1 * f1.x + w2 * f2.x + w3 * f3.x;
        ay += w0 * f0.y + w1 * f1.y + w2 * f2.y + w3 * f3.y;
    }
    for (; j < end; ++j) {
        float2 f = __half22float2(hp[(size_t)g_srcs[j] * (CH/2) + c]);
        ax += g_ws[j] * f.x;
        ay += g_ws[j] * f.y;
    }
    reinterpret_cast<__half2*>(tx)[(size_t)d * (CH/2) + c] = __floats2half2_rn(ax, ay);
}

// ---------------- fp16 tensor GEMM: h2 = relu(h@W0 + tx1@W1 + b1) -----------
// M=10000 (79 CTAs of 128), N=128, K=2 phases x 256. A direct cp.async (fp16).
#define G2_STG   20480
#define G2_SMEM  (2 * G2_STG)

__global__ void __launch_bounds__(256, 2)
k_gemm2_h(const __half* __restrict__ A0, const __half* __restrict__ A1h,
          const float* __restrict__ bias, __half* __restrict__ C16) {
    extern __shared__ char smem[];
    const uint32_t sb = smem_u32(smem);
    const int tid  = threadIdx.x;
    const int wid  = tid >> 5, lane = tid & 31;
    const int warp_m = (wid >> 1) * 32;
    const int warp_n = (wid & 1) * 64;
    const int m0 = blockIdx.x * 128;

    const int blr = tid >> 1;
    const int blh = tid & 1;

    const int La     = lane & 7;
    const int a_moff = ((lane >> 3) & 1) * 8 + La;
    const int a_koff = (lane >> 4) * 8;
    const int b_noff = (lane >> 4) * 8 + La;
    const int b_koff = ((lane >> 3) & 1) * 8;

    float acc[2][8][4];
#pragma unroll
    for (int i = 0; i < 2; i++)
#pragma unroll
        for (int j = 0; j < 8; j++)
#pragma unroll
            for (int q = 0; q < 4; q++) acc[i][j][q] = 0.0f;

#define ISSUE2(c, st) do {                                                      \
        int ph_ = (c) >> 3;                                                     \
        int k0_ = ((c) & 7) * BKC;                                              \
        const __half* As_ = ph_ ? A1h : A0;                                     \
        uint32_t stg_ = sb + (uint32_t)(st) * G2_STG;                           \
        {                                                                       \
            uint32_t da_ = stg_ + (uint32_t)(blr * PITCH + blh * 32);           \
            const char* sa_ = (const char*)(As_ + (size_t)(m0 + blr) * 256 + k0_) + blh * 32; \
            int sz_ = (m0 + blr < NN_NODES) ? 16 : 0;                           \
            CP16Z(da_, sa_, sz_);  CP16Z(da_ + 16, sa_ + 16, sz_);              \
        }                                                                       \
        {                                                                       \
            uint32_t db_ = stg_ + 10240u + (uint32_t)(blr * PITCH + blh * 32);  \
            const char* sb_ = (const char*)(g_W2h + (size_t)ph_ * 128 * 256     \
                                            + (size_t)blr * 256 + k0_) + blh * 32; \
            CP16(db_, sb_);  CP16(db_ + 16, sb_ + 16);                          \
        }                                                                       \
        CP_COMMIT();                                                            \
    } while (0)

    ISSUE2(0, 0);
    for (int c = 0; c < 16; ++c) {
        CP_WAIT0();
        __syncthreads();
        if (c + 1 < 16) ISSUE2(c + 1, (c + 1) & 1);

        const uint32_t abase = sb + (uint32_t)(c & 1) * G2_STG;
        const uint32_t bbase = abase + 10240u;
#pragma unroll
        for (int ks = 0; ks < 2; ++ks) {
            const int kb = ks * 16;
            uint32_t ah[2][4];
#pragma unroll
            for (int mt = 0; mt < 2; ++mt) {
                uint32_t ra = abase + (uint32_t)((warp_m + mt * 16 + a_moff) * PITCH + (kb + a_koff) * 2);
                ldm_x4(ah[mt][0], ah[mt][1], ah[mt][2], ah[mt][3], ra);
            }
#pragma unroll
            for (int bb = 0; bb < 4; ++bb) {
                uint32_t bh[4];
                uint32_t rb = bbase + (uint32_t)((warp_n + bb * 16 + b_noff) * PITCH + (kb + b_koff) * 2);
                ldm_x4(bh[0], bh[1], bh[2], bh[3], rb);
#pragma unroll
                for (int mt = 0; mt < 2; ++mt)
#pragma unroll
                    for (int hf = 0; hf < 2; ++hf)
                        mma16816h(acc[mt][bb * 2 + hf], ah[mt], &bh[hf * 2]);
            }
        }
        __syncthreads();
    }
#undef ISSUE2

    // epilogue: bias + relu -> h2 fp16
    const int gg = lane >> 2;
    const int t2 = (lane & 3) * 2;
    __half2* cp = reinterpret_cast<__half2*>(C16);
#pragma unroll
    for (int nt = 0; nt < 8; ++nt) {
        int n = warp_n + nt * 8 + t2;
        float b0 = bias[n], b1 = bias[n + 1];
#pragma unroll
        for (int mt = 0; mt < 2; ++mt) {
            int ma = m0 + warp_m + mt * 16 + gg;
            if (ma < NN_NODES)
                cp[(size_t)ma * 64 + (n >> 1)] = __floats2half2_rn(
                    fmaxf(acc[mt][nt][0] + b0, 0.f), fmaxf(acc[mt][nt][1] + b1, 0.f));
            int mb = ma + 8;
            if (mb < NN_NODES)
                cp[(size_t)mb * 64 + (n >> 1)] = __floats2half2_rn(
                    fmaxf(acc[mt][nt][2] + b0, 0.f), fmaxf(acc[mt][nt][3] + b1, 0.f));
        }
    }
}

// ---------------- fp16 tensor dual GEMM: mu (cols 0-63) + logstd (64-127) ---
// M=10000 (79 CTAs), N=128, K=2 phases x 128. Output fp32 to d_out.
__global__ void __launch_bounds__(256, 2)
k_dual_h(const __half* __restrict__ A0, const __half* __restrict__ A1h,
         const float* __restrict__ bm, const float* __restrict__ bl,
         float* __restrict__ Cm, float* __restrict__ Cl) {
    extern __shared__ char smem[];
    const uint32_t sb = smem_u32(smem);
    const int tid  = threadIdx.x;
    const int wid  = tid >> 5, lane = tid & 31;
    const int warp_m = (wid >> 1) * 32;
    const int warp_n = (wid & 1) * 64;      // 0 -> mu, 64 -> ls
    const int m0 = blockIdx.x * 128;

    const int blr = tid >> 1;
    const int blh = tid & 1;

    const int La     = lane & 7;
    const int a_moff = ((lane >> 3) & 1) * 8 + La;
    const int a_koff = (lane >> 4) * 8;
    const int b_noff = (lane >> 4) * 8 + La;
    const int b_koff = ((lane >> 3) & 1) * 8;

    float acc[2][8][4];
#pragma unroll
    for (int i = 0; i < 2; i++)
#pragma unroll
        for (int j = 0; j < 8; j++)
#pragma unroll
            for (int q = 0; q < 4; q++) acc[i][j][q] = 0.0f;

#define ISSUED(c, st) do {                                                      \
        int ph_ = (c) >> 2;                                                     \
        int k0_ = ((c) & 3) * BKC;                                              \
        const __half* As_ = ph_ ? A1h : A0;                                     \
        uint32_t stg_ = sb + (uint32_t)(st) * G2_STG;                           \
        {                                                                       \
            uint32_t da_ = stg_ + (uint32_t)(blr * PITCH + blh * 32);           \
            const char* sa_ = (const char*)(As_ + (size_t)(m0 + blr) * 128 + k0_) + blh * 32; \
            int sz_ = (m0 + blr < NN_NODES) ? 16 : 0;                           \
            CP16Z(da_, sa_, sz_);  CP16Z(da_ + 16, sa_ + 16, sz_);              \
        }                                                                       \
        {                                                                       \
            uint32_t db_ = stg_ + 10240u + (uint32_t)(blr * PITCH + blh * 32);  \
            const char* sb_ = (const char*)(g_Wdh + (size_t)ph_ * 128 * 128     \
                                            + (size_t)blr * 128 + k0_) + blh * 32; \
            CP16(db_, sb_);  CP16(db_ + 16, sb_ + 16);                          \
        }                                                                       \
        CP_COMMIT();                                                            \
    } while (0)

    ISSUED(0, 0);
    for (int c = 0; c < 8; ++c) {
        CP_WAIT0();
        __syncthreads();
        if (c + 1 < 8) ISSUED(c + 1, (c + 1) & 1);

        const uint32_t abase = sb + (uint32_t)(c & 1) * G2_STG;
        const uint32_t bbase = abase + 10240u;
#pragma unroll
        for (int ks = 0; ks < 2; ++ks) {
            const int kb = ks * 16;
            uint32_t ah[2][4];
#pragma unroll
            for (int mt = 0; mt < 2; ++mt) {
                uint32_t ra = abase + (uint32_t)((warp_m + mt * 16 + a_moff) * PITCH + (kb + a_koff) * 2);
                ldm_x4(ah[mt][0], ah[mt][1], ah[mt][2], ah[mt][3], ra);
            }
#pragma unroll
            for (int bb = 0; bb < 4; ++bb) {
                uint32_t bh[4];
                uint32_t rb = bbase + (uint32_t)((warp_n + bb * 16 + b_noff) * PITCH + (kb + b_koff) * 2);
                ldm_x4(bh[0], bh[1], bh[2], bh[3], rb);
#pragma unroll
                for (int mt = 0; mt < 2; ++mt)
#pragma unroll
                    for (int hf = 0; hf < 2; ++hf)
                        mma16816h(acc[mt][bb * 2 + hf], ah[mt], &bh[hf * 2]);
            }
        }
        __syncthreads();
    }
#undef ISSUED

    // epilogue: warp_n==0 -> mu, warp_n==64 -> ls; fp32 output
    const int gg = lane >> 2;
    const int t2 = (lane & 3) * 2;
    const bool isMu = (warp_n == 0);
    float* Cdst = isMu ? Cm : Cl;
    const float* bdst = isMu ? bm : bl;
#pragma unroll
    for (int nt = 0; nt < 8; ++nt) {
        int n = nt * 8 + t2;                 // 0..62 within the 64
        float b0 = bdst[n], b1 = bdst[n + 1];
#pragma unroll
        for (int mt = 0; mt < 2; ++mt) {
            int ma = m0 + warp_m + mt * 16 + gg;
            if (ma < NN_NODES) {
                float2 o; o.x = acc[mt][nt][0] + b0; o.y = acc[mt][nt][1] + b1;
                *reinterpret_cast<float2*>(Cdst + (size_t)ma * 64 + n) = o;
            }
            int mb = ma + 8;
            if (mb < NN_NODES) {
                float2 o; o.x = acc[mt][nt][2] + b0; o.y = acc[mt][nt][3] + b1;
                *reinterpret_cast<float2*>(Cdst + (size_t)mb * 64 + n) = o;
            }
        }
    }
}

// ---------------- launcher --------------------------------------------------
extern "C" void kernel_launch(void* const* d_in, const int* in_sizes, int n_in,
                              void* d_out, int out_size) {
    const float* x    = (const float*)d_in[0];
    const int*   ei   = (const int*)d_in[1];
    const float* Wt   = (const float*)d_in[2];
    const float* bt   = (const float*)d_in[3];
    const float* W0_1 = (const float*)d_in[4];
    const float* W1_1 = (const float*)d_in[5];
    const float* b1   = (const float*)d_in[6];
    const float* W0mu = (const float*)d_in[7];
    const float* W1mu = (const float*)d_in[8];
    const float* bmu  = (const float*)d_in[9];
    const float* W0ls = (const float*)d_in[10];
    const float* W1ls = (const float*)d_in[11];
    const float* bls  = (const float*)d_in[12];
    float* out = (float*)d_out;

    float* h = nullptr;
    __half *h16, *tx116, *h216, *tx216;
    cudaGetSymbolAddress((void**)&h,     g_h);
    cudaGetSymbolAddress((void**)&h16,   g_h16);
    cudaGetSymbolAddress((void**)&tx116, g_tx116);
    cudaGetSymbolAddress((void**)&h216,  g_h216);
    cudaGetSymbolAddress((void**)&tx216, g_tx216);

    cudaFuncSetAttribute(k_gemm1_mma, cudaFuncAttributeMaxDynamicSharedMemorySize, G1_SMEM);
    cudaFuncSetAttribute(k_gemm2_h,   cudaFuncAttributeMaxDynamicSharedMemorySize, G2_SMEM);
    cudaFuncSetAttribute(k_dual_h,    cudaFuncAttributeMaxDynamicSharedMemorySize, G2_SMEM);

    const int TPB = 256;

    // GEMM1 deps first; k_gemm1_mma stays at launch index 3 (ncu samples it)
    {
        dim3 grid(KPAD / 32, 256 / 32), blk(32, 32);
        k_convW<<<grid, blk>>>(Wt);                                  // 0
    }
    k_zeroH<<<(NN_NODES * IN_C / 4 + TPB - 1) / TPB, TPB>>>();       // 1
    k_zero_deg<<<(NN_NODES + TPB - 1) / TPB, TPB>>>(NN_NODES);       // 2
    k_gemm1_mma<<<NCTAS, 256, G1_SMEM>>>(x, h);                      // 3
    k_combine<<<(NN_NODES * IN_C / 4 + TPB - 1) / TPB, TPB>>>(bt, h, h16);
    k_count<<<(NE + TPB - 1) / TPB, TPB>>>(ei);
    k_dinv<<<(NN_NODES + TPB - 1) / TPB, TPB>>>(NN_NODES);
    k_scan<<<1, 1024>>>(NN_NODES);
    k_bucket<<<(NE + TPB - 1) / TPB, TPB>>>(ei);

    // weight conversions (independent, cheap)
    {
        dim3 grid(8, 4, 2), blk(32, 32);
        k_convW2<<<grid, blk>>>(W0_1, W1_1);
    }
    {
        dim3 grid(4, 4, 2), blk(32, 32);
        k_convWd<<<grid, blk>>>(W0mu, W1mu, W0ls, W1ls);
    }

    // tx1 = L_hat @ h  (fp16)
    k_spmm_h<IN_C><<<NN_NODES, IN_C / 2>>>(h16, tx116);

    // h2 = relu(h @ W0_1 + tx1 @ W1_1 + b1) on tensor cores -> fp16
    k_gemm2_h<<<MB79, 256, G2_SMEM>>>(h16, tx116, b1, h216);

    // tx2 = L_hat @ h2 (fp16)
    k_spmm_h<C1><<<NN_NODES, C1 / 2>>>(h216, tx216);

    // mu / logstd on tensor cores -> fp32 out
    k_dual_h<<<MB79, 256, G2_SMEM>>>(h216, tx216, bmu, bls,
                                     out, out + (size_t)NN_NODES * OUT_C);
}

// round 17
// speedup vs baseline: 2.0664x; 1.0910x over previous
#include <cuda_runtime.h>
#include <cuda_fp16.h>
#include <cstdint>
#include <cstddef>

// ---------------- problem constants ----------------
#define NN_NODES 10000
#define IN_C     256
#define C1       128
#define OUT_C    64
#define NE       640000
#define KPAD     10048          // padded K for B (zero-filled)
#define BKC      32             // K per mainloop chunk
#define CH1      313            // ceil(10000/32)
#define NTILES   158            // 79 m-blocks (128 rows) x 2 n-blocks (128 cols)
#define GWORK    ((long)NTILES * CH1)
#define NCTAS    296            // 148 SMs x 2 CTAs/SM, one wave
#define MB79     79             // ceil(10000/128)

// ---------------- PTX helpers ----------------
__device__ __forceinline__ uint32_t smem_u32(const void* p) {
    uint32_t a;
    asm("{ .reg .u64 t; cvta.to.shared.u64 t, %1; cvt.u32.u64 %0, t; }" : "=r"(a) : "l"(p));
    return a;
}
__device__ __forceinline__ void ldm_x4(uint32_t& r0, uint32_t& r1, uint32_t& r2, uint32_t& r3,
                                       uint32_t addr) {
    asm volatile("ldmatrix.sync.aligned.m8n8.x4.shared.b16 {%0,%1,%2,%3}, [%4];"
                 : "=r"(r0), "=r"(r1), "=r"(r2), "=r"(r3) : "r"(addr));
}
__device__ __forceinline__ void mma16816h(float* d, const uint32_t* a, const uint32_t* b) {
    asm volatile("mma.sync.aligned.m16n8k16.row.col.f32.f16.f16.f32 "
                 "{%0,%1,%2,%3}, {%4,%5,%6,%7}, {%8,%9}, {%0,%1,%2,%3};"
                 : "+f"(d[0]), "+f"(d[1]), "+f"(d[2]), "+f"(d[3])
                 : "r"(a[0]), "r"(a[1]), "r"(a[2]), "r"(a[3]), "r"(b[0]), "r"(b[1]));
}
#define CP16(dst, src) \
    asm volatile("cp.async.cg.shared.global [%0], [%1], 16;" :: "r"(dst), "l"(src))
#define CP16Z(dst, src, sz) \
    asm volatile("cp.async.cg.shared.global [%0], [%1], 16, %2;" :: "r"(dst), "l"(src), "r"(sz))
#define CP_COMMIT() asm volatile("cp.async.commit_group;")
#define CP_WAIT0()  asm volatile("cp.async.wait_group 0;")

// ---------------- scratch globals ----------------
__device__ float  g_h   [NN_NODES * IN_C];       // fp32 atomic accum for GEMM1
__device__ __half g_h16 [NN_NODES * IN_C];       // h as fp16
__device__ __half g_tx116[NN_NODES * IN_C];      // tx1 fp16
__device__ __half g_h216[NN_NODES * C1];         // h2 fp16
__device__ __half g_tx216[NN_NODES * C1];        // tx2 fp16
__device__ int   g_outdeg[NN_NODES];
__device__ int   g_indeg [NN_NODES];
__device__ float g_dinv  [NN_NODES];
__device__ int   g_rowstart[NN_NODES + 1];
__device__ int   g_cursor  [NN_NODES];
__device__ int   g_srcs [NE];
__device__ float g_ws   [NE];
__device__ __half g_BTh[256 * KPAD];             // Wt^T fp16 [n][k]
__device__ __half g_W2h[2 * 128 * 256];          // {W0_1,W1_1}^T fp16 [ph][n][k]
__device__ __half g_Wdh[2 * 128 * 128];          // {[Wmu;Wls]}^T fp16 [ph][n][k]

// ---------------- preprocessing kernels ----------------
// merged: zero fp32 H accumulator + degree arrays
__global__ void k_zero() {
    int i = blockIdx.x * blockDim.x + threadIdx.x;
    if (i < NN_NODES * IN_C / 4)
        reinterpret_cast<float4*>(g_h)[i] = make_float4(0.f, 0.f, 0.f, 0.f);
    if (i < NN_NODES) { g_outdeg[i] = 0; g_indeg[i] = 0; }
}
__global__ void k_count(const int* __restrict__ ei) {
    int e = blockIdx.x * blockDim.x + threadIdx.x;
    if (e < NE) {
        atomicAdd(&g_outdeg[ei[e]], 1);
        atomicAdd(&g_indeg[ei[NE + e]], 1);
    }
}
__global__ void k_dinv(int n) {
    int i = blockIdx.x * blockDim.x + threadIdx.x;
    if (i < n) {
        int d = g_outdeg[i];
        g_dinv[i] = (d > 0) ? rsqrtf((float)d) : 0.0f;
    }
}
__global__ void k_scan(int n) {
    __shared__ int sh[1024];
    int t = threadIdx.x;
    const int per = 10;
    int base = t * per;
    int loc[10];
    int s = 0;
#pragma unroll
    for (int i = 0; i < per; i++) {
        int idx = base + i;
        int v = (idx < n) ? g_indeg[idx] : 0;
        loc[i] = s; s += v;
    }
    sh[t] = s;
    __syncthreads();
    for (int off = 1; off < 1024; off <<= 1) {
        int v = (t >= off) ? sh[t - off] : 0;
        __syncthreads();
        sh[t] += v;
        __syncthreads();
    }
    int bb = (t > 0) ? sh[t - 1] : 0;
#pragma unroll
    for (int i = 0; i < per; i++) {
        int idx = base + i;
        if (idx < n) { int v = bb + loc[i]; g_rowstart[idx] = v; g_cursor[idx] = v; }
    }
    if (t == 1023) g_rowstart[n] = sh[1023];
}
__global__ void k_bucket(const int* __restrict__ ei) {
    int e = blockIdx.x * blockDim.x + threadIdx.x;
    if (e < NE) {
        int s = ei[e];
        int d = ei[NE + e];
        int pos = atomicAdd(&g_cursor[d], 1);
        g_srcs[pos] = s;
        g_ws[pos]   = -g_dinv[s] * g_dinv[d];
    }
}

// Wt [10000,256] fp32 -> transposed fp16 [256][KPAD]
__global__ void k_convW(const float* __restrict__ Wt) {
    __shared__ float tile[32][33];
    int bx = blockIdx.x, by = blockIdx.y;
    int tx = threadIdx.x, ty = threadIdx.y;
    int gk = bx * 32 + ty;
    int gn = by * 32 + tx;
    tile[ty][tx] = (gk < NN_NODES) ? Wt[(size_t)gk * 256 + gn] : 0.0f;
    __syncthreads();
    int n = by * 32 + ty;
    int k = bx * 32 + tx;
    g_BTh[(size_t)n * KPAD + k] = __float2half(tile[tx][ty]);
}

// W0_1/W1_1 [256,128] -> g_W2h[ph][n(128)][k(256)] fp16
__global__ void k_convW2(const float* __restrict__ W0, const float* __restrict__ W1) {
    __shared__ float tile[32][33];
    int ph = blockIdx.z;
    const float* W = ph ? W1 : W0;
    int k0 = blockIdx.x * 32, n0 = blockIdx.y * 32;
    int tx = threadIdx.x, ty = threadIdx.y;
    tile[ty][tx] = W[(size_t)(k0 + ty) * 128 + n0 + tx];
    __syncthreads();
    g_W2h[(size_t)ph * 128 * 256 + (size_t)(n0 + ty) * 256 + k0 + tx] =
        __float2half(tile[tx][ty]);
}

// Wmu/Wls [128,64] -> g_Wdh[ph][n(128: 0-63 mu,64-127 ls)][k(128)] fp16
__global__ void k_convWd(const float* __restrict__ W0m, const float* __restrict__ W1m,
                         const float* __restrict__ W0l, const float* __restrict__ W1l) {
    __shared__ float tile[32][33];
    int ph = blockIdx.z;
    int nb = blockIdx.y;                 // 0..3
    const float* W = (nb < 2) ? (ph ? W1m : W0m) : (ph ? W1l : W0l);
    int k0 = blockIdx.x * 32;
    int nc0 = (nb & 1) * 32;
    int tx = threadIdx.x, ty = threadIdx.y;
    tile[ty][tx] = W[(size_t)(k0 + ty) * 64 + nc0 + tx];
    __syncthreads();
    g_Wdh[(size_t)ph * 128 * 128 + (size_t)(nb * 32 + ty) * 128 + k0 + tx] =
        __float2half(tile[tx][ty]);
}

// ---------------- GEMM1 via mma.sync FP16 (unchanged, R14/R15 winner) -------
#define G1_STG   20480
#define G1_SMEM  (2 * G1_STG)
#define PITCH    80

__global__ void __launch_bounds__(256, 2)
k_gemm1_mma(const float* __restrict__ X, float* __restrict__ P) {
    extern __shared__ char smem[];
    const uint32_t sb = smem_u32(smem);
    const int tid  = threadIdx.x;
    const int wid  = tid >> 5, lane = tid & 31;
    const int warp_m = (wid >> 1) * 32;
    const int warp_n = (wid & 1) * 64;

    const int alr = tid >> 1;
    const int alq = tid & 1;
    const int blr = tid >> 1;
    const int blh = tid & 1;

    const int La     = lane & 7;
    const int a_moff = ((lane >> 3) & 1) * 8 + La;
    const int a_koff = (lane >> 4) * 8;
    const int b_noff = (lane >> 4) * 8 + La;
    const int b_koff = ((lane >> 3) & 1) * 8;

    const char* bsrc = (const char*)g_BTh;
    const size_t brow = (size_t)KPAD * 2;

    float4 v[4];
    float acc[2][8][4];

    long g  = (long)blockIdx.x * GWORK / NCTAS;
    long g1 = (long)(blockIdx.x + 1) * GWORK / NCTAS;

    while (g < g1) {
        const int t   = (int)(g / CH1);
        const int cst = (int)(g % CH1);
        int cend = CH1;
        {
            long avail = g1 - g;
            if ((long)(CH1 - cst) > avail) cend = cst + (int)avail;
        }
        const int m0  = (t >> 1) * 128;
        const int n0g = (t & 1) * 128;

#pragma unroll
        for (int i = 0; i < 2; i++)
#pragma unroll
            for (int j = 0; j < 8; j++)
#pragma unroll
                for (int q = 0; q < 4; q++) acc[i][j][q] = 0.0f;

#define LDG_A(c) do {                                                           \
        int k0 = (c) * BKC;                                                     \
        int grow = m0 + alr;                                                    \
        _Pragma("unroll")                                                       \
        for (int i = 0; i < 4; i++) {                                           \
            int gk = k0 + alq * 16 + i * 4;                                     \
            v[i] = (grow < NN_NODES && gk < NN_NODES)                           \
                 ? *reinterpret_cast<const float4*>(X + (size_t)grow * NN_NODES + gk) \
                 : make_float4(0.f, 0.f, 0.f, 0.f);                             \
        }                                                                       \
    } while (0)

#define CPA_B(c, st) do {                                                       \
        int k0 = (c) * BKC;                                                     \
        uint32_t dsth = sb + (st) * G1_STG + 10240 + blr * PITCH + blh * 32;    \
        const char* sh_ = bsrc + (size_t)(n0g + blr) * brow + k0 * 2 + blh * 32; \
        CP16(dsth, sh_);  CP16(dsth + 16, sh_ + 16);                            \
        CP_COMMIT();                                                            \
    } while (0)

#define STS_A(st) do {                                                          \
        uint32_t dh = sb + (st) * G1_STG + alr * PITCH + alq * 32;              \
        uint32_t hA[8];                                                         \
        _Pragma("unroll")                                                       \
        for (int i = 0; i < 4; i++) {                                           \
            __half h0 = __float2half(v[i].x);                                   \
            __half h1 = __float2half(v[i].y);                                   \
            __half h2 = __float2half(v[i].z);                                   \
            __half h3 = __float2half(v[i].w);                                   \
            hA[i*2+0] = (uint32_t)__half_as_ushort(h0) | ((uint32_t)__half_as_ushort(h1) << 16); \
            hA[i*2+1] = (uint32_t)__half_as_ushort(h2) | ((uint32_t)__half_as_ushort(h3) << 16); \
        }                                                                       \
        asm volatile("st.shared.v4.b32 [%0], {%1,%2,%3,%4};"                    \
            :: "r"(dh), "r"(hA[0]), "r"(hA[1]), "r"(hA[2]), "r"(hA[3]));        \
        asm volatile("st.shared.v4.b32 [%0], {%1,%2,%3,%4};"                    \
            :: "r"(dh + 16), "r"(hA[4]), "r"(hA[5]), "r"(hA[6]), "r"(hA[7]));   \
    } while (0)

        LDG_A(cst);
        CPA_B(cst, 0);
        STS_A(0);
        CP_WAIT0();
        __syncthreads();

        for (int c = cst; c < cend; ++c) {
            const int st  = (c - cst) & 1;
            const int nst = st ^ 1;
            const bool pre = (c + 1 < cend);
            if (pre) { LDG_A(c + 1); CPA_B(c + 1, nst); }

            const uint32_t abase = sb + st * G1_STG;
            const uint32_t bbase = abase + 10240;
#pragma unroll
            for (int ks = 0; ks < 2; ++ks) {
                const int kb = ks * 16;
                uint32_t ah[2][4];
#pragma unroll
                for (int mt = 0; mt < 2; ++mt) {
                    uint32_t ra = abase + (uint32_t)((warp_m + mt * 16 + a_moff) * PITCH + (kb + a_koff) * 2);
                    ldm_x4(ah[mt][0], ah[mt][1], ah[mt][2], ah[mt][3], ra);
                }
#pragma unroll
                for (int bb = 0; bb < 4; ++bb) {
                    uint32_t bh[4];
                    uint32_t rb = bbase + (uint32_t)((warp_n + bb * 16 + b_noff) * PITCH + (kb + b_koff) * 2);
                    ldm_x4(bh[0], bh[1], bh[2], bh[3], rb);
#pragma unroll
                    for (int mt = 0; mt < 2; ++mt)
#pragma unroll
                        for (int hf = 0; hf < 2; ++hf)
                            mma16816h(acc[mt][bb * 2 + hf], ah[mt], &bh[hf * 2]);
                }
            }

            if (pre) { STS_A(nst); CP_WAIT0(); }
            __syncthreads();
        }
#undef LDG_A
#undef CPA_B
#undef STS_A

        {
            const int gg = lane >> 2;
            const int t2 = (lane & 3) * 2;
#pragma unroll
            for (int nt = 0; nt < 8; ++nt) {
                int n = n0g + warp_n + nt * 8 + t2;
#pragma unroll
                for (int mt = 0; mt < 2; ++mt) {
                    int ma = m0 + warp_m + mt * 16 + gg;
                    if (ma < NN_NODES) {
                        atomicAdd(&P[(size_t)ma * 256 + n],     acc[mt][nt][0]);
                        atomicAdd(&P[(size_t)ma * 256 + n + 1], acc[mt][nt][1]);
                    }
                    int mb = ma + 8;
                    if (mb < NN_NODES) {
                        atomicAdd(&P[(size_t)mb * 256 + n],     acc[mt][nt][2]);
                        atomicAdd(&P[(size_t)mb * 256 + n + 1], acc[mt][nt][3]);
                    }
                }
            }
        }
        g += (long)(cend - cst);
    }
}

// h16 = fp16(relu(h + bias))
__global__ void k_combine(const float* __restrict__ bt, const float* __restrict__ Hf,
                          __half* __restrict__ H16) {
    int i = blockIdx.x * blockDim.x + threadIdx.x;
    if (i < NN_NODES * IN_C / 4) {
        float4 a = reinterpret_cast<const float4*>(Hf)[i];
        int col = (i * 4) & 255;
        float v0 = fmaxf(a.x + bt[col + 0], 0.f);
        float v1 = fmaxf(a.y + bt[col + 1], 0.f);
        float v2 = fmaxf(a.z + bt[col + 2], 0.f);
        float v3 = fmaxf(a.w + bt[col + 3], 0.f);
        __half2* p = reinterpret_cast<__half2*>(H16);
        p[i * 2 + 0] = __floats2half2_rn(v0, v1);
        p[i * 2 + 1] = __floats2half2_rn(v2, v3);
    }
}

// ---------------- SpMM fp16: block per dst row, thread per half2 channel ----
template <int CH>
__global__ void __launch_bounds__(CH / 2) k_spmm_h(const __half* __restrict__ h,
                                                   __half* __restrict__ tx) {
    int d = blockIdx.x;
    int c = threadIdx.x;
    const __half2* hp = reinterpret_cast<const __half2*>(h);
    int beg = g_rowstart[d];
    int end = g_rowstart[d + 1];
    float ax = 0.f, ay = 0.f;
    int j = beg;
    for (; j + 4 <= end; j += 4) {
        int   s0 = g_srcs[j],   s1 = g_srcs[j+1], s2 = g_srcs[j+2], s3 = g_srcs[j+3];
        float w0 = g_ws[j],     w1 = g_ws[j+1],   w2 = g_ws[j+2],   w3 = g_ws[j+3];
        float2 f0 = __half22float2(hp[(size_t)s0 * (CH/2) + c]);
        float2 f1 = __half22float2(hp[(size_t)s1 * (CH/2) + c]);
        float2 f2 = __half22float2(hp[(size_t)s2 * (CH/2) + c]);
        float2 f3 = __half22float2(hp[(size_t)s3 * (CH/2) + c]);
        ax += w0 * f0.x + w1 * f1.x + w2 * f2.x + w3 * f3.x;
        ay += w0 * f0.y + w1 * f1.y + w2 * f2.y + w3 * f3.y;
    }
    for (; j < end; ++j) {
        float2 f = __half22float2(hp[(size_t)g_srcs[j] * (CH/2) + c]);
        ax += g_ws[j] * f.x;
        ay += g_ws[j] * f.y;
    }
    reinterpret_cast<__half2*>(tx)[(size_t)d * (CH/2) + c] = __floats2half2_rn(ax, ay);
}

// ---------------- fp16 tensor GEMM: h2 = relu(h@W0 + tx1@W1 + b1) -----------
#define G2_STG   20480
#define G2_SMEM  (2 * G2_STG)

__global__ void __launch_bounds__(256, 2)
k_gemm2_h(const __half* __restrict__ A0, const __half* __restrict__ A1h,
          const float* __restrict__ bias, __half* __restrict__ C16) {
    extern __shared__ char smem[];
    const uint32_t sb = smem_u32(smem);
    const int tid  = threadIdx.x;
    const int wid  = tid >> 5, lane = tid & 31;
    const int warp_m = (wid >> 1) * 32;
    const int warp_n = (wid & 1) * 64;
    const int m0 = blockIdx.x * 128;

    const int blr = tid >> 1;
    const int blh = tid & 1;

    const int La     = lane & 7;
    const int a_moff = ((lane >> 3) & 1) * 8 + La;
    const int a_koff = (lane >> 4) * 8;
    const int b_noff = (lane >> 4) * 8 + La;
    const int b_koff = ((lane >> 3) & 1) * 8;

    float acc[2][8][4];
#pragma unroll
    for (int i = 0; i < 2; i++)
#pragma unroll
        for (int j = 0; j < 8; j++)
#pragma unroll
            for (int q = 0; q < 4; q++) acc[i][j][q] = 0.0f;

#define ISSUE2(c, st) do {                                                      \
        int ph_ = (c) >> 3;                                                     \
        int k0_ = ((c) & 7) * BKC;                                              \
        const __half* As_ = ph_ ? A1h : A0;                                     \
        uint32_t stg_ = sb + (uint32_t)(st) * G2_STG;                           \
        {                                                                       \
            uint32_t da_ = stg_ + (uint32_t)(blr * PITCH + blh * 32);           \
            const char* sa_ = (const char*)(As_ + (size_t)(m0 + blr) * 256 + k0_) + blh * 32; \
            int sz_ = (m0 + blr < NN_NODES) ? 16 : 0;                           \
            CP16Z(da_, sa_, sz_);  CP16Z(da_ + 16, sa_ + 16, sz_);              \
        }                                                                       \
        {                                                                       \
            uint32_t db_ = stg_ + 10240u + (uint32_t)(blr * PITCH + blh * 32);  \
            const char* sb_ = (const char*)(g_W2h + (size_t)ph_ * 128 * 256     \
                                            + (size_t)blr * 256 + k0_) + blh * 32; \
            CP16(db_, sb_);  CP16(db_ + 16, sb_ + 16);                          \
        }                                                                       \
        CP_COMMIT();                                                            \
    } while (0)

    ISSUE2(0, 0);
    for (int c = 0; c < 16; ++c) {
        CP_WAIT0();
        __syncthreads();
        if (c + 1 < 16) ISSUE2(c + 1, (c + 1) & 1);

        const uint32_t abase = sb + (uint32_t)(c & 1) * G2_STG;
        const uint32_t bbase = abase + 10240u;
#pragma unroll
        for (int ks = 0; ks < 2; ++ks) {
            const int kb = ks * 16;
            uint32_t ah[2][4];
#pragma unroll
            for (int mt = 0; mt < 2; ++mt) {
                uint32_t ra = abase + (uint32_t)((warp_m + mt * 16 + a_moff) * PITCH + (kb + a_koff) * 2);
                ldm_x4(ah[mt][0], ah[mt][1], ah[mt][2], ah[mt][3], ra);
            }
#pragma unroll
            for (int bb = 0; bb < 4; ++bb) {
                uint32_t bh[4];
                uint32_t rb = bbase + (uint32_t)((warp_n + bb * 16 + b_noff) * PITCH + (kb + b_koff) * 2);
                ldm_x4(bh[0], bh[1], bh[2], bh[3], rb);
#pragma unroll
                for (int mt = 0; mt < 2; ++mt)
#pragma unroll
                    for (int hf = 0; hf < 2; ++hf)
                        mma16816h(acc[mt][bb * 2 + hf], ah[mt], &bh[hf * 2]);
            }
        }
        __syncthreads();
    }
#undef ISSUE2

    const int gg = lane >> 2;
    const int t2 = (lane & 3) * 2;
    __half2* cp = reinterpret_cast<__half2*>(C16);
#pragma unroll
    for (int nt = 0; nt < 8; ++nt) {
        int n = warp_n + nt * 8 + t2;
        float b0 = bias[n], b1 = bias[n + 1];
#pragma unroll
        for (int mt = 0; mt < 2; ++mt) {
            int ma = m0 + warp_m + mt * 16 + gg;
            if (ma < NN_NODES)
                cp[(size_t)ma * 64 + (n >> 1)] = __floats2half2_rn(
                    fmaxf(acc[mt][nt][0] + b0, 0.f), fmaxf(acc[mt][nt][1] + b1, 0.f));
            int mb = ma + 8;
            if (mb < NN_NODES)
                cp[(size_t)mb * 64 + (n >> 1)] = __floats2half2_rn(
                    fmaxf(acc[mt][nt][2] + b0, 0.f), fmaxf(acc[mt][nt][3] + b1, 0.f));
        }
    }
}

// ---------------- fp16 tensor dual GEMM: mu (cols 0-63) + logstd (64-127) ---
__global__ void __launch_bounds__(256, 2)
k_dual_h(const __half* __restrict__ A0, const __half* __restrict__ A1h,
         const float* __restrict__ bm, const float* __restrict__ bl,
         float* __restrict__ Cm, float* __restrict__ Cl) {
    extern __shared__ char smem[];
    const uint32_t sb = smem_u32(smem);
    const int tid  = threadIdx.x;
    const int wid  = tid >> 5, lane = tid & 31;
    const int warp_m = (wid >> 1) * 32;
    const int warp_n = (wid & 1) * 64;
    const int m0 = blockIdx.x * 128;

    const int blr = tid >> 1;
    const int blh = tid & 1;

    const int La     = lane & 7;
    const int a_moff = ((lane >> 3) & 1) * 8 + La;
    const int a_koff = (lane >> 4) * 8;
    const int b_noff = (lane >> 4) * 8 + La;
    const int b_koff = ((lane >> 3) & 1) * 8;

    float acc[2][8][4];
#pragma unroll
    for (int i = 0; i < 2; i++)
#pragma unroll
        for (int j = 0; j < 8; j++)
#pragma unroll
            for (int q = 0; q < 4; q++) acc[i][j][q] = 0.0f;

#define ISSUED(c, st) do {                                                      \
        int ph_ = (c) >> 2;                                                     \
        int k0_ = ((c) & 3) * BKC;                                              \
        const __half* As_ = ph_ ? A1h : A0;                                     \
        uint32_t stg_ = sb + (uint32_t)(st) * G2_STG;                           \
        {                                                                       \
            uint32_t da_ = stg_ + (uint32_t)(blr * PITCH + blh * 32);           \
            const char* sa_ = (const char*)(As_ + (size_t)(m0 + blr) * 128 + k0_) + blh * 32; \
            int sz_ = (m0 + blr < NN_NODES) ? 16 : 0;                           \
            CP16Z(da_, sa_, sz_);  CP16Z(da_ + 16, sa_ + 16, sz_);              \
        }                                                                       \
        {                                                                       \
            uint32_t db_ = stg_ + 10240u + (uint32_t)(blr * PITCH + blh * 32);  \
            const char* sb_ = (const char*)(g_Wdh + (size_t)ph_ * 128 * 128     \
                                            + (size_t)blr * 128 + k0_) + blh * 32; \
            CP16(db_, sb_);  CP16(db_ + 16, sb_ + 16);                          \
        }                                                                       \
        CP_COMMIT();                                                            \
    } while (0)

    ISSUED(0, 0);
    for (int c = 0; c < 8; ++c) {
        CP_WAIT0();
        __syncthreads();
        if (c + 1 < 8) ISSUED(c + 1, (c + 1) & 1);

        const uint32_t abase = sb + (uint32_t)(c & 1) * G2_STG;
        const uint32_t bbase = abase + 10240u;
#pragma unroll
        for (int ks = 0; ks < 2; ++ks) {
            const int kb = ks * 16;
            uint32_t ah[2][4];
#pragma unroll
            for (int mt = 0; mt < 2; ++mt) {
                uint32_t ra = abase + (uint32_t)((warp_m + mt * 16 + a_moff) * PITCH + (kb + a_koff) * 2);
                ldm_x4(ah[mt][0], ah[mt][1], ah[mt][2], ah[mt][3], ra);
            }
#pragma unroll
            for (int bb = 0; bb < 4; ++bb) {
                uint32_t bh[4];
                uint32_t rb = bbase + (uint32_t)((warp_n + bb * 16 + b_noff) * PITCH + (kb + b_koff) * 2);
                ldm_x4(bh[0], bh[1], bh[2], bh[3], rb);
#pragma unroll
                for (int mt = 0; mt < 2; ++mt)
#pragma unroll
                    for (int hf = 0; hf < 2; ++hf)
                        mma16816h(acc[mt][bb * 2 + hf], ah[mt], &bh[hf * 2]);
            }
        }
        __syncthreads();
    }
#undef ISSUED

    const int gg = lane >> 2;
    const int t2 = (lane & 3) * 2;
    const bool isMu = (warp_n == 0);
    float* Cdst = isMu ? Cm : Cl;
    const float* bdst = isMu ? bm : bl;
#pragma unroll
    for (int nt = 0; nt < 8; ++nt) {
        int n = nt * 8 + t2;
        float b0 = bdst[n], b1 = bdst[n + 1];
#pragma unroll
        for (int mt = 0; mt < 2; ++mt) {
            int ma = m0 + warp_m + mt * 16 + gg;
            if (ma < NN_NODES) {
                float2 o; o.x = acc[mt][nt][0] + b0; o.y = acc[mt][nt][1] + b1;
                *reinterpret_cast<float2*>(Cdst + (size_t)ma * 64 + n) = o;
            }
            int mb = ma + 8;
            if (mb < NN_NODES) {
                float2 o; o.x = acc[mt][nt][2] + b0; o.y = acc[mt][nt][3] + b1;
                *reinterpret_cast<float2*>(Cdst + (size_t)mb * 64 + n) = o;
            }
        }
    }
}

// ---------------- launcher --------------------------------------------------
extern "C" void kernel_launch(void* const* d_in, const int* in_sizes, int n_in,
                              void* d_out, int out_size) {
    const float* x    = (const float*)d_in[0];
    const int*   ei   = (const int*)d_in[1];
    const float* Wt   = (const float*)d_in[2];
    const float* bt   = (const float*)d_in[3];
    const float* W0_1 = (const float*)d_in[4];
    const float* W1_1 = (const float*)d_in[5];
    const float* b1   = (const float*)d_in[6];
    const float* W0mu = (const float*)d_in[7];
    const float* W1mu = (const float*)d_in[8];
    const float* bmu  = (const float*)d_in[9];
    const float* W0ls = (const float*)d_in[10];
    const float* W1ls = (const float*)d_in[11];
    const float* bls  = (const float*)d_in[12];
    float* out = (float*)d_out;

    float* h = nullptr;
    __half *h16, *tx116, *h216, *tx216;
    cudaGetSymbolAddress((void**)&h,     g_h);
    cudaGetSymbolAddress((void**)&h16,   g_h16);
    cudaGetSymbolAddress((void**)&tx116, g_tx116);
    cudaGetSymbolAddress((void**)&h216,  g_h216);
    cudaGetSymbolAddress((void**)&tx216, g_tx216);

    cudaFuncSetAttribute(k_gemm1_mma, cudaFuncAttributeMaxDynamicSharedMemorySize, G1_SMEM);
    cudaFuncSetAttribute(k_gemm2_h,   cudaFuncAttributeMaxDynamicSharedMemorySize, G2_SMEM);
    cudaFuncSetAttribute(k_dual_h,    cudaFuncAttributeMaxDynamicSharedMemorySize, G2_SMEM);

    // side stream + events, created once (host-side resources only)
    static cudaStream_t s_side = nullptr;
    static cudaEvent_t  ev_fork = nullptr, ev_join = nullptr;
    if (s_side == nullptr) {
        cudaStreamCreateWithFlags(&s_side, cudaStreamNonBlocking);
        cudaEventCreateWithFlags(&ev_fork, cudaEventDisableTiming);
        cudaEventCreateWithFlags(&ev_join, cudaEventDisableTiming);
    }

    const int TPB = 256;

    // ---- main stream: GEMM1 dependencies ----
    {
        dim3 grid(KPAD / 32, 256 / 32), blk(32, 32);
        k_convW<<<grid, blk>>>(Wt);
    }
    k_zero<<<(NN_NODES * IN_C / 4 + TPB - 1) / TPB, TPB>>>();

    // ---- fork: independent graph preprocessing + weight conversions ----
    cudaEventRecord(ev_fork, 0);
    cudaStreamWaitEvent(s_side, ev_fork, 0);
    k_count<<<(NE + TPB - 1) / TPB, TPB, 0, s_side>>>(ei);
    k_dinv<<<(NN_NODES + TPB - 1) / TPB, TPB, 0, s_side>>>(NN_NODES);
    k_scan<<<1, 1024, 0, s_side>>>(NN_NODES);
    k_bucket<<<(NE + TPB - 1) / TPB, TPB, 0, s_side>>>(ei);
    {
        dim3 grid(8, 4, 2), blk(32, 32);
        k_convW2<<<grid, blk, 0, s_side>>>(W0_1, W1_1);
    }
    {
        dim3 grid(4, 4, 2), blk(32, 32);
        k_convWd<<<grid, blk, 0, s_side>>>(W0mu, W1mu, W0ls, W1ls);
    }
    cudaEventRecord(ev_join, s_side);

    // ---- main stream: GEMM1 (overlaps side chain) ----
    k_gemm1_mma<<<NCTAS, 256, G1_SMEM>>>(x, h);
    k_combine<<<(NN_NODES * IN_C / 4 + TPB - 1) / TPB, TPB>>>(bt, h, h16);

    // ---- join before SpMM (needs bucket output) ----
    cudaStreamWaitEvent(0, ev_join, 0);

    // tx1 = L_hat @ h  (fp16)
    k_spmm_h<IN_C><<<NN_NODES, IN_C / 2>>>(h16, tx116);

    // h2 = relu(h @ W0_1 + tx1 @ W1_1 + b1) on tensor cores -> fp16
    k_gemm2_h<<<MB79, 256, G2_SMEM>>>(h16, tx116, b1, h216);

    // tx2 = L_hat @ h2 (fp16)
    k_spmm_h<C1><<<NN_NODES, C1 / 2>>>(h216, tx216);

    // mu / logstd on tensor cores -> fp32 out
    k_dual_h<<<MB79, 256, G2_SMEM>>>(h216, tx216, bmu, bls,
                                     out, out + (size_t)NN_NODES * OUT_C);
}